// round 5
// baseline (speedup 1.0000x reference)
#include <cuda_runtime.h>
#include <cuda_bf16.h>
#include <math.h>
#include <stdint.h>

#define B_  2
#define S_  2048
#define D_  1024
#define H_  16
#define DEPTH_ 64
#define MROWS (B_*S_)          // 4096
#define KDIM 1024
#define NBH (B_*H_)            // 32
#define NQB (S_/64)            // 32
#define NTRI (NQB*(NQB+1)/2)   // 528
#define OUT_ELEMS  ((size_t)B_*S_*D_)            // 4194304
#define ATTN_ELEMS ((size_t)B_*H_*S_*S_)         // 134217728

// ---- static device scratch (allocation-free rule) ----
__device__ float g_qh[B_*H_*S_*DEPTH_];
__device__ float g_kh[B_*H_*S_*DEPTH_];
__device__ float g_vh[B_*H_*S_*DEPTH_];
__device__ float g_pre[B_*S_*D_];
__device__ float g_attn_fallback[1];
__device__ __align__(256) __nv_bfloat16 g_xhi[MROWS*KDIM];
__device__ __align__(256) __nv_bfloat16 g_xlo[MROWS*KDIM];
__device__ __align__(256) __nv_bfloat16 g_wthi[KDIM*KDIM];
__device__ __align__(256) __nv_bfloat16 g_wtlo[KDIM*KDIM];
__device__ float g_rmax[NBH*S_*NQB];     // per (bh,row,kblock) block max
__device__ float g_rsum[NBH*S_*NQB];     // per (bh,row,kblock) block expsum
__device__ float g_rowM[NBH*S_];
__device__ float g_rowInvS[NBH*S_];

// ============================================================
// HMMA helpers
// ============================================================
__device__ __forceinline__ uint32_t lds_addr(const void* p) {
    return (uint32_t)__cvta_generic_to_shared(p);
}

#define LDSM4(r, addr) \
    asm volatile("ldmatrix.sync.aligned.m8n8.x4.shared.b16 {%0,%1,%2,%3}, [%4];" \
        : "=r"((r)[0]), "=r"((r)[1]), "=r"((r)[2]), "=r"((r)[3]) : "r"(addr))

#define MMA16816(c, a, b0, b1) \
    asm volatile("mma.sync.aligned.m16n8k16.row.col.f32.bf16.bf16.f32 " \
        "{%0,%1,%2,%3}, {%4,%5,%6,%7}, {%8,%9}, {%0,%1,%2,%3};" \
        : "+f"((c)[0]), "+f"((c)[1]), "+f"((c)[2]), "+f"((c)[3]) \
        : "r"((a)[0]), "r"((a)[1]), "r"((a)[2]), "r"((a)[3]), "r"(b0), "r"(b1))

// ============================================================
// Split fp32 -> bf16 hi/lo
// ============================================================
__global__ void split_kernel(const float4* __restrict__ x,
                             uint2* __restrict__ hi, uint2* __restrict__ lo, int n4)
{
    int i = blockIdx.x*256 + threadIdx.x;
    if (i >= n4) return;
    float4 v = x[i];
    __nv_bfloat16 h0 = __float2bfloat16(v.x), h1 = __float2bfloat16(v.y);
    __nv_bfloat16 h2 = __float2bfloat16(v.z), h3 = __float2bfloat16(v.w);
    __nv_bfloat16 l0 = __float2bfloat16(v.x - __bfloat162float(h0));
    __nv_bfloat16 l1 = __float2bfloat16(v.y - __bfloat162float(h1));
    __nv_bfloat16 l2 = __float2bfloat16(v.z - __bfloat162float(h2));
    __nv_bfloat16 l3 = __float2bfloat16(v.w - __bfloat162float(h3));
    union { __nv_bfloat16 h[4]; uint2 u; } ph, pl;
    ph.h[0]=h0; ph.h[1]=h1; ph.h[2]=h2; ph.h[3]=h3;
    pl.h[0]=l0; pl.h[1]=l1; pl.h[2]=l2; pl.h[3]=l3;
    hi[i] = ph.u;
    lo[i] = pl.u;
}

// ============================================================
// W [k][n] fp32 -> W^T hi/lo bf16 [n][k]
// ============================================================
__global__ void wsplit_kernel(const float* __restrict__ W,
                              __nv_bfloat16* __restrict__ thi,
                              __nv_bfloat16* __restrict__ tlo)
{
    __shared__ float ts[32][33];
    const int k0 = blockIdx.x*32, n0 = blockIdx.y*32;
    const int tx = threadIdx.x, ty = threadIdx.y;
    #pragma unroll
    for (int u = 0; u < 4; ++u)
        ts[ty + 8*u][tx] = W[(size_t)(k0 + ty + 8*u)*KDIM + n0 + tx];
    __syncthreads();
    #pragma unroll
    for (int u = 0; u < 4; ++u) {
        float v = ts[tx][ty + 8*u];
        __nv_bfloat16 h = __float2bfloat16(v);
        __nv_bfloat16 l = __float2bfloat16(v - __bfloat162float(h));
        size_t idx = (size_t)(n0 + ty + 8*u)*KDIM + k0 + tx;
        thi[idx] = h;
        tlo[idx] = l;
    }
}

// ============================================================
// HMMA split-bf16 GEMM (unchanged from R4 — passing)
// ============================================================
#define PADE 40

__global__ void __launch_bounds__(256)
gemm_hmma(const __nv_bfloat16* __restrict__ Ahi,
          const __nv_bfloat16* __restrict__ Alo,
          const __nv_bfloat16* __restrict__ Bhi,
          const __nv_bfloat16* __restrict__ Blo,
          const float* __restrict__ bias,
          float* __restrict__ out, int headed)
{
    __shared__ __nv_bfloat16 As_hi[128*PADE];
    __shared__ __nv_bfloat16 As_lo[128*PADE];
    __shared__ __nv_bfloat16 Bs_hi[128*PADE];
    __shared__ __nv_bfloat16 Bs_lo[128*PADE];

    const int tid = threadIdx.x;
    const int wid = tid >> 5, lane = tid & 31;
    const int wy = wid & 3;
    const int wx = wid >> 2;
    const int m0 = blockIdx.y * 128;
    const int n0 = blockIdx.x * 128;

    float acc[2][8][4];
    #pragma unroll
    for (int mi = 0; mi < 2; ++mi)
        #pragma unroll
        for (int ni = 0; ni < 8; ++ni)
            #pragma unroll
            for (int c = 0; c < 4; ++c) acc[mi][ni][c] = 0.f;

    for (int kt = 0; kt < KDIM/32; ++kt) {
        __syncthreads();
        #pragma unroll
        for (int u = 0; u < 2; ++u) {
            int idx = tid + 256*u;
            int r = idx >> 2, c = idx & 3;
            size_t ga = (size_t)(m0 + r)*KDIM + kt*32 + c*8;
            size_t gb = (size_t)(n0 + r)*KDIM + kt*32 + c*8;
            int so = r*PADE + c*8;
            *(uint4*)&As_hi[so] = *(const uint4*)&Ahi[ga];
            *(uint4*)&As_lo[so] = *(const uint4*)&Alo[ga];
            *(uint4*)&Bs_hi[so] = *(const uint4*)&Bhi[gb];
            *(uint4*)&Bs_lo[so] = *(const uint4*)&Blo[gb];
        }
        __syncthreads();

        #pragma unroll
        for (int ks = 0; ks < 2; ++ks) {
            uint32_t ahi[2][4], alo[2][4], bhi[4][4], blo[4][4];
            {
                int koff = ks*16 + (lane >> 4)*8;
                int r = wy*32 + (lane & 15);
                LDSM4(ahi[0], lds_addr(&As_hi[r*PADE + koff]));
                LDSM4(ahi[1], lds_addr(&As_hi[(r+16)*PADE + koff]));
                LDSM4(alo[0], lds_addr(&As_lo[r*PADE + koff]));
                LDSM4(alo[1], lds_addr(&As_lo[(r+16)*PADE + koff]));
            }
            {
                int nl = (lane & 7) + ((lane >> 4) << 3);
                int kc = ks*16 + ((lane >> 3) & 1)*8;
                #pragma unroll
                for (int p = 0; p < 4; ++p) {
                    int nr = wx*64 + p*16 + nl;
                    LDSM4(bhi[p], lds_addr(&Bs_hi[nr*PADE + kc]));
                    LDSM4(blo[p], lds_addr(&Bs_lo[nr*PADE + kc]));
                }
            }
            #pragma unroll
            for (int mi = 0; mi < 2; ++mi) {
                #pragma unroll
                for (int p = 0; p < 4; ++p) {
                    MMA16816(acc[mi][2*p],   ahi[mi], bhi[p][0], bhi[p][1]);
                    MMA16816(acc[mi][2*p+1], ahi[mi], bhi[p][2], bhi[p][3]);
                    MMA16816(acc[mi][2*p],   ahi[mi], blo[p][0], blo[p][1]);
                    MMA16816(acc[mi][2*p+1], ahi[mi], blo[p][2], blo[p][3]);
                    MMA16816(acc[mi][2*p],   alo[mi], bhi[p][0], bhi[p][1]);
                    MMA16816(acc[mi][2*p+1], alo[mi], bhi[p][2], bhi[p][3]);
                }
            }
        }
    }

    const int lr = lane >> 2, lc = (lane & 3)*2;
    #pragma unroll
    for (int mi = 0; mi < 2; ++mi) {
        #pragma unroll
        for (int ni = 0; ni < 8; ++ni) {
            int col = n0 + wx*64 + ni*8 + lc;
            float b0 = bias[col], b1 = bias[col+1];
            #pragma unroll
            for (int half = 0; half < 2; ++half) {
                int row = m0 + wy*32 + mi*16 + lr + half*8;
                float v0 = acc[mi][ni][half*2]   + b0;
                float v1 = acc[mi][ni][half*2+1] + b1;
                if (headed) {
                    int b = row >> 11, s = row & 2047;
                    int h = col >> 6, d = col & 63;
                    out[(((size_t)(b*H_ + h))*S_ + s)*DEPTH_ + d]     = v0;
                    out[(((size_t)(b*H_ + h))*S_ + s)*DEPTH_ + d + 1] = v1;
                } else {
                    *(float2*)&out[(size_t)row*D_ + col] = make_float2(v0, v1);
                }
            }
        }
    }
}

// ============================================================
// Logits: lower-triangle blocks only + per (row,kblock) stats.
// grid (NTRI, NBH), block (16,16)
// ============================================================
__global__ void logits_kernel(const float* __restrict__ mask, float* __restrict__ attn)
{
    const int bh = blockIdx.y;
    const int b  = bh >> 4;
    // triangle index -> (qb, kb)
    int t = blockIdx.x;
    int qb = (int)((sqrtf(8.f*t + 1.f) - 1.f) * 0.5f);
    while ((qb+1)*(qb+2)/2 <= t) ++qb;
    while (qb*(qb+1)/2 > t) --qb;
    int kb = t - qb*(qb+1)/2;
    const int q0 = qb*64, k0 = kb*64;

    const int tx = threadIdx.x, ty = threadIdx.y;
    const int tid = ty*16 + tx;
    const float scale = 0.125f;

    __shared__ float Qs[64][65];
    __shared__ float Ks[64][65];
    const float* Q = g_qh + (size_t)bh*S_*DEPTH_;
    const float* K = g_kh + (size_t)bh*S_*DEPTH_;
    float* A = attn + (size_t)bh*S_*S_;

    #pragma unroll
    for (int u = 0; u < 16; ++u) {
        int idx = tid + 256*u;
        int r = idx >> 6;
        int d = idx & 63;
        Qs[d][r] = Q[(size_t)(q0 + r)*DEPTH_ + d];
        Ks[d][r] = K[(size_t)(k0 + r)*DEPTH_ + d];
    }
    __syncthreads();

    float acc[4][4] = {};
    #pragma unroll
    for (int d = 0; d < 64; ++d) {
        float a[4], b_[4];
        #pragma unroll
        for (int i = 0; i < 4; ++i) a[i]  = Qs[d][ty + 16*i];
        #pragma unroll
        for (int j = 0; j < 4; ++j) b_[j] = Ks[d][tx + 16*j];
        #pragma unroll
        for (int i = 0; i < 4; ++i)
            #pragma unroll
            for (int j = 0; j < 4; ++j)
                acc[i][j] += a[i]*b_[j];
    }

    float mk[4];
    #pragma unroll
    for (int j = 0; j < 4; ++j)
        mk[j] = mask[(size_t)b*S_ + k0 + tx + 16*j];

    const bool diag = (kb == qb);
    #pragma unroll
    for (int i = 0; i < 4; ++i) {
        const int qr = q0 + ty + 16*i;
        float x[4];
        #pragma unroll
        for (int j = 0; j < 4; ++j) {
            int kc = k0 + tx + 16*j;
            float causal = (diag && kc > qr) ? 1.0f : 0.0f;
            float m = fmaxf(mk[j], causal);
            x[j] = acc[i][j]*scale + m * (-1e17f);
        }
        // store raw logits
        size_t rb = (size_t)qr*S_ + k0 + tx;
        #pragma unroll
        for (int j = 0; j < 4; ++j)
            A[rb + 16*j] = x[j];

        // block-row stats over the 16 tx lanes
        float tm = fmaxf(fmaxf(x[0], x[1]), fmaxf(x[2], x[3]));
        #pragma unroll
        for (int o = 8; o > 0; o >>= 1)
            tm = fmaxf(tm, __shfl_xor_sync(0xffffffffu, tm, o));
        float se = __expf(x[0]-tm) + __expf(x[1]-tm)
                 + __expf(x[2]-tm) + __expf(x[3]-tm);
        #pragma unroll
        for (int o = 8; o > 0; o >>= 1)
            se += __shfl_xor_sync(0xffffffffu, se, o);
        if (tx == 0) {
            size_t sidx = ((size_t)bh*S_ + qr)*NQB + kb;
            g_rmax[sidx] = tm;
            g_rsum[sidx] = se;
        }
    }
}

// ============================================================
// Row stats reduce: one warp per row -> (M, 1/S)
// ============================================================
__global__ void rowstats_kernel()
{
    const int gw = blockIdx.x*8 + (threadIdx.x >> 5);   // 0..65535
    const int lane = threadIdx.x & 31;
    const int row = gw & (S_-1);
    const int n = (row >> 6) + 1;        // number of valid kblocks

    size_t base = (size_t)gw * NQB;
    float m = (lane < n) ? g_rmax[base + lane] : -INFINITY;
    float s = (lane < n) ? g_rsum[base + lane] : 0.f;

    float M = m;
    #pragma unroll
    for (int o = 16; o > 0; o >>= 1)
        M = fmaxf(M, __shfl_xor_sync(0xffffffffu, M, o));
    float sc = s * __expf(m - M);
    #pragma unroll
    for (int o = 16; o > 0; o >>= 1)
        sc += __shfl_xor_sync(0xffffffffu, sc, o);
    if (lane == 0) {
        g_rowM[gw] = M;
        g_rowInvS[gw] = 1.0f / sc;
    }
}

// ============================================================
// Fused AV + normalize: reads raw logits, writes normalized attn,
// accumulates P @ V, zero-fills upper triangle.
// grid (NQB, NBH) with reversed qblk for scheduling.
// ============================================================
__global__ void avnorm_kernel(float* __restrict__ attn)
{
    const int bh = blockIdx.y;
    const int qblk = gridDim.x - 1 - blockIdx.x;
    const int q0 = qblk*64;
    const int b = bh >> 4, h = bh & 15;
    const int tx = threadIdx.x, ty = threadIdx.y;
    const int tid = ty*16 + tx;

    __shared__ float Ps[64][65];
    __shared__ float Vs[64][65];
    __shared__ float Ms[64], Is[64];

    float* A = attn + (size_t)bh*S_*S_;
    const float* V = g_vh + (size_t)bh*S_*DEPTH_;

    if (tid < 64) {
        Ms[tid] = g_rowM[(size_t)bh*S_ + q0 + tid];
        Is[tid] = g_rowInvS[(size_t)bh*S_ + q0 + tid];
    }
    __syncthreads();

    float acc[4][4] = {};

    for (int k0 = 0; k0 <= q0; k0 += 64) {
        if (k0 > 0) __syncthreads();
        #pragma unroll
        for (int u = 0; u < 16; ++u) {
            int idx = tid + 256*u;
            int r = idx >> 6;
            int c = idx & 63;
            size_t ga = (size_t)(q0 + r)*S_ + k0 + c;
            float p = __expf(A[ga] - Ms[r]) * Is[r];
            A[ga] = p;
            Ps[r][c] = p;
            Vs[r][c] = V[(size_t)(k0 + r)*DEPTH_ + c];
        }
        __syncthreads();
        #pragma unroll
        for (int c = 0; c < 64; ++c) {
            float a[4], b_[4];
            #pragma unroll
            for (int i = 0; i < 4; ++i) a[i]  = Ps[ty + 16*i][c];
            #pragma unroll
            for (int j = 0; j < 4; ++j) b_[j] = Vs[c][tx + 16*j];
            #pragma unroll
            for (int i = 0; i < 4; ++i)
                #pragma unroll
                for (int j = 0; j < 4; ++j)
                    acc[i][j] += a[i]*b_[j];
        }
    }

    // zero-fill upper triangle of this q-block's rows
    {
        const int zstart = q0 + 64;
        if (zstart < S_) {
            const int perRow = (S_ - zstart) >> 2;
            const float4 z4 = make_float4(0.f, 0.f, 0.f, 0.f);
            for (int idx = tid; idx < 64*perRow; idx += 256) {
                int r = idx / perRow;
                int c = (idx - r*perRow) << 2;
                *(float4*)&A[(size_t)(q0 + r)*S_ + zstart + c] = z4;
            }
        }
    }

    #pragma unroll
    for (int i = 0; i < 4; ++i) {
        int s = q0 + ty + 16*i;
        #pragma unroll
        for (int j = 0; j < 4; ++j) {
            int d = tx + 16*j;
            g_pre[((size_t)b*S_ + s)*D_ + h*DEPTH_ + d] = acc[i][j];
        }
    }
}

// ============================================================
extern "C" void kernel_launch(void* const* d_in, const int* in_sizes, int n_in,
                              void* d_out, int out_size)
{
    (void)in_sizes; (void)n_in;
    const float* v    = (const float*)d_in[0];
    const float* k    = (const float*)d_in[1];
    const float* q    = (const float*)d_in[2];
    const float* mask = (const float*)d_in[3];
    const float* Wq   = (const float*)d_in[4];
    const float* bq   = (const float*)d_in[5];
    const float* Wk   = (const float*)d_in[6];
    const float* bk   = (const float*)d_in[7];
    const float* Wv   = (const float*)d_in[8];
    const float* bv   = (const float*)d_in[9];
    const float* Wo   = (const float*)d_in[10];
    const float* bo   = (const float*)d_in[11];

    float* out = (float*)d_out;

    float *qh, *kh, *vh, *pre;
    cudaGetSymbolAddress((void**)&qh, g_qh);
    cudaGetSymbolAddress((void**)&kh, g_kh);
    cudaGetSymbolAddress((void**)&vh, g_vh);
    cudaGetSymbolAddress((void**)&pre, g_pre);
    __nv_bfloat16 *xhi, *xlo, *wthi, *wtlo;
    cudaGetSymbolAddress((void**)&xhi, g_xhi);
    cudaGetSymbolAddress((void**)&xlo, g_xlo);
    cudaGetSymbolAddress((void**)&wthi, g_wthi);
    cudaGetSymbolAddress((void**)&wtlo, g_wtlo);

    float* attn;
    if ((size_t)out_size >= OUT_ELEMS + ATTN_ELEMS) {
        attn = out + OUT_ELEMS;
    } else {
        cudaGetSymbolAddress((void**)&attn, g_attn_fallback);
    }

    const int n4 = MROWS*KDIM/4;
    dim3 gsplit((n4 + 255)/256);
    dim3 gwt(32, 32), twt(32, 8);
    dim3 ggemm(KDIM/128, MROWS/128);
    dim3 tb(16, 16);

    // Q projection
    split_kernel<<<gsplit, 256>>>((const float4*)q, (uint2*)xhi, (uint2*)xlo, n4);
    wsplit_kernel<<<gwt, twt>>>(Wq, wthi, wtlo);
    gemm_hmma<<<ggemm, 256>>>(xhi, xlo, wthi, wtlo, bq, qh, 1);
    // K projection
    split_kernel<<<gsplit, 256>>>((const float4*)k, (uint2*)xhi, (uint2*)xlo, n4);
    wsplit_kernel<<<gwt, twt>>>(Wk, wthi, wtlo);
    gemm_hmma<<<ggemm, 256>>>(xhi, xlo, wthi, wtlo, bk, kh, 1);
    // V projection
    split_kernel<<<gsplit, 256>>>((const float4*)v, (uint2*)xhi, (uint2*)xlo, n4);
    wsplit_kernel<<<gwt, twt>>>(Wv, wthi, wtlo);
    gemm_hmma<<<ggemm, 256>>>(xhi, xlo, wthi, wtlo, bv, vh, 1);

    // attention: triangle logits + stats, row reduce, fused AV-normalize
    dim3 glog(NTRI, NBH);
    logits_kernel<<<glog, tb>>>(mask, attn);
    rowstats_kernel<<<NBH*S_/8, 256>>>();
    dim3 gav(NQB, NBH);
    avnorm_kernel<<<gav, tb>>>(attn);

    // output projection
    split_kernel<<<gsplit, 256>>>((const float4*)pre, (uint2*)xhi, (uint2*)xlo, n4);
    wsplit_kernel<<<gwt, twt>>>(Wo, wthi, wtlo);
    gemm_hmma<<<ggemm, 256>>>(xhi, xlo, wthi, wtlo, bo, out, 0);
}

// round 6
// speedup vs baseline: 1.2774x; 1.2774x over previous
#include <cuda_runtime.h>
#include <cuda_bf16.h>
#include <math.h>
#include <stdint.h>

#define B_  2
#define S_  2048
#define D_  1024
#define H_  16
#define DEPTH_ 64
#define MROWS (B_*S_)          // 4096
#define KDIM 1024
#define NBH (B_*H_)            // 32
#define NQB (S_/64)            // 32
#define NTRI (NQB*(NQB+1)/2)   // 528
#define OUT_ELEMS  ((size_t)B_*S_*D_)            // 4194304
#define ATTN_ELEMS ((size_t)B_*H_*S_*S_)         // 134217728

// ---- static device scratch (allocation-free rule) ----
__device__ float g_qh[B_*H_*S_*DEPTH_];
__device__ float g_kh[B_*H_*S_*DEPTH_];
__device__ float g_vh[B_*H_*S_*DEPTH_];
__device__ float g_pre[B_*S_*D_];
__device__ float g_attn_fallback[1];
__device__ __align__(256) __nv_bfloat16 g_xhi[MROWS*KDIM];
__device__ __align__(256) __nv_bfloat16 g_xlo[MROWS*KDIM];
__device__ __align__(256) __nv_bfloat16 g_wthi[KDIM*KDIM];
__device__ __align__(256) __nv_bfloat16 g_wtlo[KDIM*KDIM];
__device__ float g_rmax[NBH*S_*NQB];
__device__ float g_rsum[NBH*S_*NQB];
__device__ float g_rowM[NBH*S_];
__device__ float g_rowInvS[NBH*S_];

// ============================================================
// HMMA helpers
// ============================================================
__device__ __forceinline__ uint32_t lds_addr(const void* p) {
    return (uint32_t)__cvta_generic_to_shared(p);
}

#define LDSM4(r, addr) \
    asm volatile("ldmatrix.sync.aligned.m8n8.x4.shared.b16 {%0,%1,%2,%3}, [%4];" \
        : "=r"((r)[0]), "=r"((r)[1]), "=r"((r)[2]), "=r"((r)[3]) : "r"(addr))

#define MMA16816(c, a, b0, b1) \
    asm volatile("mma.sync.aligned.m16n8k16.row.col.f32.bf16.bf16.f32 " \
        "{%0,%1,%2,%3}, {%4,%5,%6,%7}, {%8,%9}, {%0,%1,%2,%3};" \
        : "+f"((c)[0]), "+f"((c)[1]), "+f"((c)[2]), "+f"((c)[3]) \
        : "r"((a)[0]), "r"((a)[1]), "r"((a)[2]), "r"((a)[3]), "r"(b0), "r"(b1))

// ============================================================
// Split fp32 -> bf16 hi/lo
// ============================================================
__global__ void split_kernel(const float4* __restrict__ x,
                             uint2* __restrict__ hi, uint2* __restrict__ lo, int n4)
{
    int i = blockIdx.x*256 + threadIdx.x;
    if (i >= n4) return;
    float4 v = x[i];
    __nv_bfloat16 h0 = __float2bfloat16(v.x), h1 = __float2bfloat16(v.y);
    __nv_bfloat16 h2 = __float2bfloat16(v.z), h3 = __float2bfloat16(v.w);
    __nv_bfloat16 l0 = __float2bfloat16(v.x - __bfloat162float(h0));
    __nv_bfloat16 l1 = __float2bfloat16(v.y - __bfloat162float(h1));
    __nv_bfloat16 l2 = __float2bfloat16(v.z - __bfloat162float(h2));
    __nv_bfloat16 l3 = __float2bfloat16(v.w - __bfloat162float(h3));
    union { __nv_bfloat16 h[4]; uint2 u; } ph, pl;
    ph.h[0]=h0; ph.h[1]=h1; ph.h[2]=h2; ph.h[3]=h3;
    pl.h[0]=l0; pl.h[1]=l1; pl.h[2]=l2; pl.h[3]=l3;
    hi[i] = ph.u;
    lo[i] = pl.u;
}

// ============================================================
// W [k][n] fp32 -> W^T hi/lo bf16 [n][k]
// ============================================================
__global__ void wsplit_kernel(const float* __restrict__ W,
                              __nv_bfloat16* __restrict__ thi,
                              __nv_bfloat16* __restrict__ tlo)
{
    __shared__ float ts[32][33];
    const int k0 = blockIdx.x*32, n0 = blockIdx.y*32;
    const int tx = threadIdx.x, ty = threadIdx.y;
    #pragma unroll
    for (int u = 0; u < 4; ++u)
        ts[ty + 8*u][tx] = W[(size_t)(k0 + ty + 8*u)*KDIM + n0 + tx];
    __syncthreads();
    #pragma unroll
    for (int u = 0; u < 4; ++u) {
        float v = ts[tx][ty + 8*u];
        __nv_bfloat16 h = __float2bfloat16(v);
        __nv_bfloat16 l = __float2bfloat16(v - __bfloat162float(h));
        size_t idx = (size_t)(n0 + ty + 8*u)*KDIM + k0 + tx;
        thi[idx] = h;
        tlo[idx] = l;
    }
}

// ============================================================
// HMMA split-bf16 GEMM (R4 — measured good)
// ============================================================
#define PADE 40

__global__ void __launch_bounds__(256)
gemm_hmma(const __nv_bfloat16* __restrict__ Ahi,
          const __nv_bfloat16* __restrict__ Alo,
          const __nv_bfloat16* __restrict__ Bhi,
          const __nv_bfloat16* __restrict__ Blo,
          const float* __restrict__ bias,
          float* __restrict__ out, int headed)
{
    __shared__ __nv_bfloat16 As_hi[128*PADE];
    __shared__ __nv_bfloat16 As_lo[128*PADE];
    __shared__ __nv_bfloat16 Bs_hi[128*PADE];
    __shared__ __nv_bfloat16 Bs_lo[128*PADE];

    const int tid = threadIdx.x;
    const int wid = tid >> 5, lane = tid & 31;
    const int wy = wid & 3;
    const int wx = wid >> 2;
    const int m0 = blockIdx.y * 128;
    const int n0 = blockIdx.x * 128;

    float acc[2][8][4];
    #pragma unroll
    for (int mi = 0; mi < 2; ++mi)
        #pragma unroll
        for (int ni = 0; ni < 8; ++ni)
            #pragma unroll
            for (int c = 0; c < 4; ++c) acc[mi][ni][c] = 0.f;

    for (int kt = 0; kt < KDIM/32; ++kt) {
        __syncthreads();
        #pragma unroll
        for (int u = 0; u < 2; ++u) {
            int idx = tid + 256*u;
            int r = idx >> 2, c = idx & 3;
            size_t ga = (size_t)(m0 + r)*KDIM + kt*32 + c*8;
            size_t gb = (size_t)(n0 + r)*KDIM + kt*32 + c*8;
            int so = r*PADE + c*8;
            *(uint4*)&As_hi[so] = *(const uint4*)&Ahi[ga];
            *(uint4*)&As_lo[so] = *(const uint4*)&Alo[ga];
            *(uint4*)&Bs_hi[so] = *(const uint4*)&Bhi[gb];
            *(uint4*)&Bs_lo[so] = *(const uint4*)&Blo[gb];
        }
        __syncthreads();

        #pragma unroll
        for (int ks = 0; ks < 2; ++ks) {
            uint32_t ahi[2][4], alo[2][4], bhi[4][4], blo[4][4];
            {
                int koff = ks*16 + (lane >> 4)*8;
                int r = wy*32 + (lane & 15);
                LDSM4(ahi[0], lds_addr(&As_hi[r*PADE + koff]));
                LDSM4(ahi[1], lds_addr(&As_hi[(r+16)*PADE + koff]));
                LDSM4(alo[0], lds_addr(&As_lo[r*PADE + koff]));
                LDSM4(alo[1], lds_addr(&As_lo[(r+16)*PADE + koff]));
            }
            {
                int nl = (lane & 7) + ((lane >> 4) << 3);
                int kc = ks*16 + ((lane >> 3) & 1)*8;
                #pragma unroll
                for (int p = 0; p < 4; ++p) {
                    int nr = wx*64 + p*16 + nl;
                    LDSM4(bhi[p], lds_addr(&Bs_hi[nr*PADE + kc]));
                    LDSM4(blo[p], lds_addr(&Bs_lo[nr*PADE + kc]));
                }
            }
            #pragma unroll
            for (int mi = 0; mi < 2; ++mi) {
                #pragma unroll
                for (int p = 0; p < 4; ++p) {
                    MMA16816(acc[mi][2*p],   ahi[mi], bhi[p][0], bhi[p][1]);
                    MMA16816(acc[mi][2*p+1], ahi[mi], bhi[p][2], bhi[p][3]);
                    MMA16816(acc[mi][2*p],   ahi[mi], blo[p][0], blo[p][1]);
                    MMA16816(acc[mi][2*p+1], ahi[mi], blo[p][2], blo[p][3]);
                    MMA16816(acc[mi][2*p],   alo[mi], bhi[p][0], bhi[p][1]);
                    MMA16816(acc[mi][2*p+1], alo[mi], bhi[p][2], bhi[p][3]);
                }
            }
        }
    }

    const int lr = lane >> 2, lc = (lane & 3)*2;
    #pragma unroll
    for (int mi = 0; mi < 2; ++mi) {
        #pragma unroll
        for (int ni = 0; ni < 8; ++ni) {
            int col = n0 + wx*64 + ni*8 + lc;
            float b0 = bias[col], b1 = bias[col+1];
            #pragma unroll
            for (int half = 0; half < 2; ++half) {
                int row = m0 + wy*32 + mi*16 + lr + half*8;
                float v0 = acc[mi][ni][half*2]   + b0;
                float v1 = acc[mi][ni][half*2+1] + b1;
                if (headed) {
                    int b = row >> 11, s = row & 2047;
                    int h = col >> 6, d = col & 63;
                    out[(((size_t)(b*H_ + h))*S_ + s)*DEPTH_ + d]     = v0;
                    out[(((size_t)(b*H_ + h))*S_ + s)*DEPTH_ + d + 1] = v1;
                } else {
                    *(float2*)&out[(size_t)row*D_ + col] = make_float2(v0, v1);
                }
            }
        }
    }
}

// ============================================================
// Logits: lower-triangle blocks only + per (row,kblock) stats.
// ============================================================
__global__ void logits_kernel(const float* __restrict__ mask, float* __restrict__ attn)
{
    const int bh = blockIdx.y;
    const int b  = bh >> 4;
    int t = blockIdx.x;
    int qb = (int)((sqrtf(8.f*t + 1.f) - 1.f) * 0.5f);
    while ((qb+1)*(qb+2)/2 <= t) ++qb;
    while (qb*(qb+1)/2 > t) --qb;
    int kb = t - qb*(qb+1)/2;
    const int q0 = qb*64, k0 = kb*64;

    const int tx = threadIdx.x, ty = threadIdx.y;
    const int tid = ty*16 + tx;
    const float scale = 0.125f;

    __shared__ float Qs[64][65];
    __shared__ float Ks[64][65];
    const float* Q = g_qh + (size_t)bh*S_*DEPTH_;
    const float* K = g_kh + (size_t)bh*S_*DEPTH_;
    float* A = attn + (size_t)bh*S_*S_;

    #pragma unroll
    for (int u = 0; u < 16; ++u) {
        int idx = tid + 256*u;
        int r = idx >> 6;
        int d = idx & 63;
        Qs[d][r] = Q[(size_t)(q0 + r)*DEPTH_ + d];
        Ks[d][r] = K[(size_t)(k0 + r)*DEPTH_ + d];
    }
    __syncthreads();

    float acc[4][4] = {};
    #pragma unroll
    for (int d = 0; d < 64; ++d) {
        float a[4], b_[4];
        #pragma unroll
        for (int i = 0; i < 4; ++i) a[i]  = Qs[d][ty + 16*i];
        #pragma unroll
        for (int j = 0; j < 4; ++j) b_[j] = Ks[d][tx + 16*j];
        #pragma unroll
        for (int i = 0; i < 4; ++i)
            #pragma unroll
            for (int j = 0; j < 4; ++j)
                acc[i][j] += a[i]*b_[j];
    }

    float mk[4];
    #pragma unroll
    for (int j = 0; j < 4; ++j)
        mk[j] = mask[(size_t)b*S_ + k0 + tx + 16*j];

    const bool diag = (kb == qb);
    #pragma unroll
    for (int i = 0; i < 4; ++i) {
        const int qr = q0 + ty + 16*i;
        float x[4];
        #pragma unroll
        for (int j = 0; j < 4; ++j) {
            int kc = k0 + tx + 16*j;
            float causal = (diag && kc > qr) ? 1.0f : 0.0f;
            float m = fmaxf(mk[j], causal);
            x[j] = acc[i][j]*scale + m * (-1e17f);
        }
        size_t rb = (size_t)qr*S_ + k0 + tx;
        #pragma unroll
        for (int j = 0; j < 4; ++j)
            A[rb + 16*j] = x[j];

        float tm = fmaxf(fmaxf(x[0], x[1]), fmaxf(x[2], x[3]));
        #pragma unroll
        for (int o = 8; o > 0; o >>= 1)
            tm = fmaxf(tm, __shfl_xor_sync(0xffffffffu, tm, o));
        float se = __expf(x[0]-tm) + __expf(x[1]-tm)
                 + __expf(x[2]-tm) + __expf(x[3]-tm);
        #pragma unroll
        for (int o = 8; o > 0; o >>= 1)
            se += __shfl_xor_sync(0xffffffffu, se, o);
        if (tx == 0) {
            size_t sidx = ((size_t)bh*S_ + qr)*NQB + kb;
            g_rmax[sidx] = tm;
            g_rsum[sidx] = se;
        }
    }
}

// ============================================================
// Row stats reduce: one warp per row -> (M, 1/S)
// ============================================================
__global__ void rowstats_kernel()
{
    const int gw = blockIdx.x*8 + (threadIdx.x >> 5);
    const int lane = threadIdx.x & 31;
    const int row = gw & (S_-1);
    const int n = (row >> 6) + 1;

    size_t base = (size_t)gw * NQB;
    float m = (lane < n) ? g_rmax[base + lane] : -INFINITY;
    float s = (lane < n) ? g_rsum[base + lane] : 0.f;

    float M = m;
    #pragma unroll
    for (int o = 16; o > 0; o >>= 1)
        M = fmaxf(M, __shfl_xor_sync(0xffffffffu, M, o));
    float sc = s * __expf(m - M);
    #pragma unroll
    for (int o = 16; o > 0; o >>= 1)
        sc += __shfl_xor_sync(0xffffffffu, sc, o);
    if (lane == 0) {
        g_rowM[gw] = M;
        g_rowInvS[gw] = 1.0f / sc;
    }
}

// ============================================================
// Normalize + zero-fill: uniform elementwise kernel, one float4/thread.
// Lower-triangle blocks: p = exp(x - M) * invS (masked entries underflow
// to exact 0). Upper blocks: write zeros (never read).
// ============================================================
__global__ void __launch_bounds__(256)
norm_kernel(float* __restrict__ attn)
{
    const size_t idx = (size_t)blockIdx.x*256 + threadIdx.x;   // float4 index
    const int perRow = S_/4;                                   // 512
    const size_t rowg = idx / perRow;                          // bh*S_ + qr
    const int c4 = (int)(idx - rowg*perRow);
    const int qr = (int)(rowg & (S_-1));
    const int kc = c4*4;

    float4* p = (float4*)attn + idx;
    if ((kc >> 6) <= (qr >> 6)) {
        const float M = g_rowM[rowg];
        const float I = g_rowInvS[rowg];
        float4 v = *p;
        v.x = __expf(v.x - M)*I;
        v.y = __expf(v.y - M)*I;
        v.z = __expf(v.z - M)*I;
        v.w = __expf(v.w - M)*I;
        *p = v;
    } else {
        *p = make_float4(0.f, 0.f, 0.f, 0.f);
    }
}

// ============================================================
// AV (R4, measured): reads normalized attn, causal-truncated k loop.
// ============================================================
__global__ void av_kernel(const float* __restrict__ attn)
{
    const int bh = blockIdx.y;
    const int q0 = blockIdx.x * 64;
    const int b = bh / H_, h = bh % H_;
    const int tx = threadIdx.x, ty = threadIdx.y;
    const int tid = ty*16 + tx;

    __shared__ float As[64][65];
    __shared__ float Vs[64][65];

    const float* A = attn + ((size_t)bh*S_)*S_;
    const float* V = g_vh + (size_t)bh*S_*DEPTH_;

    float acc[4][4] = {};

    for (int k0 = 0; k0 <= q0; k0 += 64) {
        #pragma unroll
        for (int t = 0; t < 16; ++t) {
            int idx = tid + 256*t;
            int r = idx >> 6;
            int c = idx & 63;
            As[r][c] = A[(size_t)(q0 + r)*S_ + k0 + c];
            Vs[r][c] = V[(size_t)(k0 + r)*DEPTH_ + c];
        }
        __syncthreads();
        #pragma unroll
        for (int c = 0; c < 64; ++c) {
            float a[4], b_[4];
            #pragma unroll
            for (int i = 0; i < 4; ++i) a[i]  = As[ty + 16*i][c];
            #pragma unroll
            for (int j = 0; j < 4; ++j) b_[j] = Vs[c][tx + 16*j];
            #pragma unroll
            for (int i = 0; i < 4; ++i)
                #pragma unroll
                for (int j = 0; j < 4; ++j)
                    acc[i][j] += a[i]*b_[j];
        }
        __syncthreads();
    }

    #pragma unroll
    for (int i = 0; i < 4; ++i) {
        int s = q0 + ty + 16*i;
        #pragma unroll
        for (int j = 0; j < 4; ++j) {
            int d = tx + 16*j;
            g_pre[((size_t)b*S_ + s)*D_ + h*DEPTH_ + d] = acc[i][j];
        }
    }
}

// ============================================================
extern "C" void kernel_launch(void* const* d_in, const int* in_sizes, int n_in,
                              void* d_out, int out_size)
{
    (void)in_sizes; (void)n_in;
    const float* v    = (const float*)d_in[0];
    const float* k    = (const float*)d_in[1];
    const float* q    = (const float*)d_in[2];
    const float* mask = (const float*)d_in[3];
    const float* Wq   = (const float*)d_in[4];
    const float* bq   = (const float*)d_in[5];
    const float* Wk   = (const float*)d_in[6];
    const float* bk   = (const float*)d_in[7];
    const float* Wv   = (const float*)d_in[8];
    const float* bv   = (const float*)d_in[9];
    const float* Wo   = (const float*)d_in[10];
    const float* bo   = (const float*)d_in[11];

    float* out = (float*)d_out;

    float *qh, *kh, *vh, *pre;
    cudaGetSymbolAddress((void**)&qh, g_qh);
    cudaGetSymbolAddress((void**)&kh, g_kh);
    cudaGetSymbolAddress((void**)&vh, g_vh);
    cudaGetSymbolAddress((void**)&pre, g_pre);
    __nv_bfloat16 *xhi, *xlo, *wthi, *wtlo;
    cudaGetSymbolAddress((void**)&xhi, g_xhi);
    cudaGetSymbolAddress((void**)&xlo, g_xlo);
    cudaGetSymbolAddress((void**)&wthi, g_wthi);
    cudaGetSymbolAddress((void**)&wtlo, g_wtlo);

    float* attn;
    if ((size_t)out_size >= OUT_ELEMS + ATTN_ELEMS) {
        attn = out + OUT_ELEMS;
    } else {
        cudaGetSymbolAddress((void**)&attn, g_attn_fallback);
    }

    const int n4 = MROWS*KDIM/4;
    dim3 gsplit((n4 + 255)/256);
    dim3 gwt(32, 32), twt(32, 8);
    dim3 ggemm(KDIM/128, MROWS/128);
    dim3 tb(16, 16);

    // Q projection
    split_kernel<<<gsplit, 256>>>((const float4*)q, (uint2*)xhi, (uint2*)xlo, n4);
    wsplit_kernel<<<gwt, twt>>>(Wq, wthi, wtlo);
    gemm_hmma<<<ggemm, 256>>>(xhi, xlo, wthi, wtlo, bq, qh, 1);
    // K projection
    split_kernel<<<gsplit, 256>>>((const float4*)k, (uint2*)xhi, (uint2*)xlo, n4);
    wsplit_kernel<<<gwt, twt>>>(Wk, wthi, wtlo);
    gemm_hmma<<<ggemm, 256>>>(xhi, xlo, wthi, wtlo, bk, kh, 1);
    // V projection
    split_kernel<<<gsplit, 256>>>((const float4*)v, (uint2*)xhi, (uint2*)xlo, n4);
    wsplit_kernel<<<gwt, twt>>>(Wv, wthi, wtlo);
    gemm_hmma<<<ggemm, 256>>>(xhi, xlo, wthi, wtlo, bv, vh, 1);

    // attention
    dim3 glog(NTRI, NBH);
    logits_kernel<<<glog, tb>>>(mask, attn);
    rowstats_kernel<<<NBH*S_/8, 256>>>();
    norm_kernel<<<(int)(ATTN_ELEMS/4/256), 256>>>(attn);
    dim3 gav(NQB, NBH);
    av_kernel<<<gav, tb>>>(attn);

    // output projection
    split_kernel<<<gsplit, 256>>>((const float4*)pre, (uint2*)xhi, (uint2*)xlo, n4);
    wsplit_kernel<<<gwt, twt>>>(Wo, wthi, wtlo);
    gemm_hmma<<<ggemm, 256>>>(xhi, xlo, wthi, wtlo, bo, out, 0);
}

// round 7
// speedup vs baseline: 1.9055x; 1.4917x over previous
#include <cuda_runtime.h>
#include <cuda_bf16.h>
#include <math.h>
#include <stdint.h>

#define B_  2
#define S_  2048
#define D_  1024
#define H_  16
#define DEPTH_ 64
#define MROWS (B_*S_)          // 4096
#define KDIM 1024
#define NBH (B_*H_)            // 32
#define NQB (S_/64)            // 32
#define NTRI (NQB*(NQB+1)/2)   // 528
#define OUT_ELEMS  ((size_t)B_*S_*D_)            // 4194304
#define ATTN_ELEMS ((size_t)B_*H_*S_*S_)         // 134217728

// ---- static device scratch ----
__device__ float g_qh[B_*H_*S_*DEPTH_];
__device__ float g_kh[B_*H_*S_*DEPTH_];
__device__ float g_vh[B_*H_*S_*DEPTH_];
__device__ float g_pre[B_*S_*D_];
__device__ float g_attn_fallback[1];
__device__ __align__(256) __nv_bfloat16 g_xhi[MROWS*KDIM];
__device__ __align__(256) __nv_bfloat16 g_xlo[MROWS*KDIM];
__device__ __align__(256) __nv_bfloat16 g_wthi[KDIM*KDIM];
__device__ __align__(256) __nv_bfloat16 g_wtlo[KDIM*KDIM];
__device__ __align__(256) __nv_bfloat16 g_qbhi[NBH*S_*DEPTH_];
__device__ __align__(256) __nv_bfloat16 g_qblo[NBH*S_*DEPTH_];
__device__ __align__(256) __nv_bfloat16 g_kbhi[NBH*S_*DEPTH_];
__device__ __align__(256) __nv_bfloat16 g_kblo[NBH*S_*DEPTH_];
__device__ __align__(256) __nv_bfloat16 g_vthi[NBH*DEPTH_*S_];   // [bh][d][s]
__device__ __align__(256) __nv_bfloat16 g_vtlo[NBH*DEPTH_*S_];
__device__ float g_rsum[NBH*S_*NQB];
__device__ float g_rowInvS[NBH*S_];

// ============================================================
// HMMA helpers
// ============================================================
__device__ __forceinline__ uint32_t lds_addr(const void* p) {
    return (uint32_t)__cvta_generic_to_shared(p);
}

#define LDSM4(r, addr) \
    asm volatile("ldmatrix.sync.aligned.m8n8.x4.shared.b16 {%0,%1,%2,%3}, [%4];" \
        : "=r"((r)[0]), "=r"((r)[1]), "=r"((r)[2]), "=r"((r)[3]) : "r"(addr))

#define MMA16816(c, a, b0, b1) \
    asm volatile("mma.sync.aligned.m16n8k16.row.col.f32.bf16.bf16.f32 " \
        "{%0,%1,%2,%3}, {%4,%5,%6,%7}, {%8,%9}, {%0,%1,%2,%3};" \
        : "+f"((c)[0]), "+f"((c)[1]), "+f"((c)[2]), "+f"((c)[3]) \
        : "r"((a)[0]), "r"((a)[1]), "r"((a)[2]), "r"((a)[3]), "r"(b0), "r"(b1))

__device__ __forceinline__ uint32_t pack_hilo(float e) {
    __nv_bfloat16 h = __float2bfloat16(e);
    __nv_bfloat16 l = __float2bfloat16(e - __bfloat162float(h));
    return ((uint32_t)__bfloat16_as_ushort(h) << 16) | (uint32_t)__bfloat16_as_ushort(l);
}

// ============================================================
// Split fp32 -> bf16 hi/lo
// ============================================================
__global__ void split_kernel(const float4* __restrict__ x,
                             uint2* __restrict__ hi, uint2* __restrict__ lo, int n4)
{
    int i = blockIdx.x*256 + threadIdx.x;
    if (i >= n4) return;
    float4 v = x[i];
    __nv_bfloat16 h0 = __float2bfloat16(v.x), h1 = __float2bfloat16(v.y);
    __nv_bfloat16 h2 = __float2bfloat16(v.z), h3 = __float2bfloat16(v.w);
    __nv_bfloat16 l0 = __float2bfloat16(v.x - __bfloat162float(h0));
    __nv_bfloat16 l1 = __float2bfloat16(v.y - __bfloat162float(h1));
    __nv_bfloat16 l2 = __float2bfloat16(v.z - __bfloat162float(h2));
    __nv_bfloat16 l3 = __float2bfloat16(v.w - __bfloat162float(h3));
    union { __nv_bfloat16 h[4]; uint2 u; } ph, pl;
    ph.h[0]=h0; ph.h[1]=h1; ph.h[2]=h2; ph.h[3]=h3;
    pl.h[0]=l0; pl.h[1]=l1; pl.h[2]=l2; pl.h[3]=l3;
    hi[i] = ph.u;
    lo[i] = pl.u;
}

// ============================================================
// W [k][n] fp32 -> W^T hi/lo bf16 [n][k]
// ============================================================
__global__ void wsplit_kernel(const float* __restrict__ W,
                              __nv_bfloat16* __restrict__ thi,
                              __nv_bfloat16* __restrict__ tlo)
{
    __shared__ float ts[32][33];
    const int k0 = blockIdx.x*32, n0 = blockIdx.y*32;
    const int tx = threadIdx.x, ty = threadIdx.y;
    #pragma unroll
    for (int u = 0; u < 4; ++u)
        ts[ty + 8*u][tx] = W[(size_t)(k0 + ty + 8*u)*KDIM + n0 + tx];
    __syncthreads();
    #pragma unroll
    for (int u = 0; u < 4; ++u) {
        float v = ts[tx][ty + 8*u];
        __nv_bfloat16 h = __float2bfloat16(v);
        __nv_bfloat16 l = __float2bfloat16(v - __bfloat162float(h));
        size_t idx = (size_t)(n0 + ty + 8*u)*KDIM + k0 + tx;
        thi[idx] = h;
        tlo[idx] = l;
    }
}

// ============================================================
// V [bh][s][d] -> V^T hi/lo bf16 [bh][d][s]
// grid (S/32, 2, NBH), block (32,8)
// ============================================================
__global__ void vtsplit_kernel()
{
    __shared__ float ts[32][33];
    const int s0 = blockIdx.x*32, d0 = blockIdx.y*32;
    const int bh = blockIdx.z;
    const int tx = threadIdx.x, ty = threadIdx.y;
    const float* V = g_vh + (size_t)bh*S_*DEPTH_;
    #pragma unroll
    for (int u = 0; u < 4; ++u)
        ts[ty + 8*u][tx] = V[(size_t)(s0 + ty + 8*u)*DEPTH_ + d0 + tx];
    __syncthreads();
    #pragma unroll
    for (int u = 0; u < 4; ++u) {
        float v = ts[tx][ty + 8*u];
        __nv_bfloat16 h = __float2bfloat16(v);
        __nv_bfloat16 l = __float2bfloat16(v - __bfloat162float(h));
        size_t idx = ((size_t)bh*DEPTH_ + d0 + ty + 8*u)*S_ + s0 + tx;
        g_vthi[idx] = h;
        g_vtlo[idx] = l;
    }
}

// ============================================================
// HMMA split-bf16 GEMM (R4 — measured good)
// ============================================================
#define PADE 40

__global__ void __launch_bounds__(256)
gemm_hmma(const __nv_bfloat16* __restrict__ Ahi,
          const __nv_bfloat16* __restrict__ Alo,
          const __nv_bfloat16* __restrict__ Bhi,
          const __nv_bfloat16* __restrict__ Blo,
          const float* __restrict__ bias,
          float* __restrict__ out, int headed)
{
    __shared__ __nv_bfloat16 As_hi[128*PADE];
    __shared__ __nv_bfloat16 As_lo[128*PADE];
    __shared__ __nv_bfloat16 Bs_hi[128*PADE];
    __shared__ __nv_bfloat16 Bs_lo[128*PADE];

    const int tid = threadIdx.x;
    const int wid = tid >> 5, lane = tid & 31;
    const int wy = wid & 3;
    const int wx = wid >> 2;
    const int m0 = blockIdx.y * 128;
    const int n0 = blockIdx.x * 128;

    float acc[2][8][4];
    #pragma unroll
    for (int mi = 0; mi < 2; ++mi)
        #pragma unroll
        for (int ni = 0; ni < 8; ++ni)
            #pragma unroll
            for (int c = 0; c < 4; ++c) acc[mi][ni][c] = 0.f;

    for (int kt = 0; kt < KDIM/32; ++kt) {
        __syncthreads();
        #pragma unroll
        for (int u = 0; u < 2; ++u) {
            int idx = tid + 256*u;
            int r = idx >> 2, c = idx & 3;
            size_t ga = (size_t)(m0 + r)*KDIM + kt*32 + c*8;
            size_t gb = (size_t)(n0 + r)*KDIM + kt*32 + c*8;
            int so = r*PADE + c*8;
            *(uint4*)&As_hi[so] = *(const uint4*)&Ahi[ga];
            *(uint4*)&As_lo[so] = *(const uint4*)&Alo[ga];
            *(uint4*)&Bs_hi[so] = *(const uint4*)&Bhi[gb];
            *(uint4*)&Bs_lo[so] = *(const uint4*)&Blo[gb];
        }
        __syncthreads();

        #pragma unroll
        for (int ks = 0; ks < 2; ++ks) {
            uint32_t ahi[2][4], alo[2][4], bhi[4][4], blo[4][4];
            {
                int koff = ks*16 + (lane >> 4)*8;
                int r = wy*32 + (lane & 15);
                LDSM4(ahi[0], lds_addr(&As_hi[r*PADE + koff]));
                LDSM4(ahi[1], lds_addr(&As_hi[(r+16)*PADE + koff]));
                LDSM4(alo[0], lds_addr(&As_lo[r*PADE + koff]));
                LDSM4(alo[1], lds_addr(&As_lo[(r+16)*PADE + koff]));
            }
            {
                int nl = (lane & 7) + ((lane >> 4) << 3);
                int kc = ks*16 + ((lane >> 3) & 1)*8;
                #pragma unroll
                for (int p = 0; p < 4; ++p) {
                    int nr = wx*64 + p*16 + nl;
                    LDSM4(bhi[p], lds_addr(&Bs_hi[nr*PADE + kc]));
                    LDSM4(blo[p], lds_addr(&Bs_lo[nr*PADE + kc]));
                }
            }
            #pragma unroll
            for (int mi = 0; mi < 2; ++mi) {
                #pragma unroll
                for (int p = 0; p < 4; ++p) {
                    MMA16816(acc[mi][2*p],   ahi[mi], bhi[p][0], bhi[p][1]);
                    MMA16816(acc[mi][2*p+1], ahi[mi], bhi[p][2], bhi[p][3]);
                    MMA16816(acc[mi][2*p],   ahi[mi], blo[p][0], blo[p][1]);
                    MMA16816(acc[mi][2*p+1], ahi[mi], blo[p][2], blo[p][3]);
                    MMA16816(acc[mi][2*p],   alo[mi], bhi[p][0], bhi[p][1]);
                    MMA16816(acc[mi][2*p+1], alo[mi], bhi[p][2], bhi[p][3]);
                }
            }
        }
    }

    const int lr = lane >> 2, lc = (lane & 3)*2;
    #pragma unroll
    for (int mi = 0; mi < 2; ++mi) {
        #pragma unroll
        for (int ni = 0; ni < 8; ++ni) {
            int col = n0 + wx*64 + ni*8 + lc;
            float b0 = bias[col], b1 = bias[col+1];
            #pragma unroll
            for (int half = 0; half < 2; ++half) {
                int row = m0 + wy*32 + mi*16 + lr + half*8;
                float v0 = acc[mi][ni][half*2]   + b0;
                float v1 = acc[mi][ni][half*2+1] + b1;
                if (headed) {
                    int b = row >> 11, s = row & 2047;
                    int h = col >> 6, d = col & 63;
                    out[(((size_t)(b*H_ + h))*S_ + s)*DEPTH_ + d]     = v0;
                    out[(((size_t)(b*H_ + h))*S_ + s)*DEPTH_ + d + 1] = v1;
                } else {
                    *(float2*)&out[(size_t)row*D_ + col] = make_float2(v0, v1);
                }
            }
        }
    }
}

// ============================================================
// HMMA logits: lower-triangle 64x64 blocks. Computes e=exp(logit+mask),
// writes packed bf16(hi,lo) into attn buffer, accumulates row sums.
// grid (NTRI, NBH), 256 threads.
// ============================================================
#define LPAD 72

__global__ void __launch_bounds__(256)
logits_hmma(const float* __restrict__ mask, uint32_t* __restrict__ attnp)
{
    const int bh = blockIdx.y;
    const int b  = bh >> 4;
    int t = blockIdx.x;
    int qb = (int)((sqrtf(8.f*t + 1.f) - 1.f) * 0.5f);
    while ((qb+1)*(qb+2)/2 <= t) ++qb;
    while (qb*(qb+1)/2 > t) --qb;
    const int kb = t - qb*(qb+1)/2;
    const int q0 = qb*64, k0 = kb*64;

    const int tid = threadIdx.x;
    const int wid = tid >> 5, lane = tid & 31;
    const int wy = wid & 3, wx = wid >> 2;

    __shared__ __nv_bfloat16 Qhi[64*LPAD], Qlo[64*LPAD];
    __shared__ __nv_bfloat16 Khi[64*LPAD], Klo[64*LPAD];
    __shared__ float bsum[2][64];

    const __nv_bfloat16* Qh = g_qbhi + ((size_t)bh*S_ + q0)*DEPTH_;
    const __nv_bfloat16* Ql = g_qblo + ((size_t)bh*S_ + q0)*DEPTH_;
    const __nv_bfloat16* Kh = g_kbhi + ((size_t)bh*S_ + k0)*DEPTH_;
    const __nv_bfloat16* Kl = g_kblo + ((size_t)bh*S_ + k0)*DEPTH_;

    #pragma unroll
    for (int u = 0; u < 2; ++u) {
        int idx = tid + 256*u;          // 0..511
        int r = idx >> 3, c = (idx & 7)*8;
        *(uint4*)&Qhi[r*LPAD + c] = *(const uint4*)&Qh[r*DEPTH_ + c];
        *(uint4*)&Qlo[r*LPAD + c] = *(const uint4*)&Ql[r*DEPTH_ + c];
        *(uint4*)&Khi[r*LPAD + c] = *(const uint4*)&Kh[r*DEPTH_ + c];
        *(uint4*)&Klo[r*LPAD + c] = *(const uint4*)&Kl[r*DEPTH_ + c];
    }
    __syncthreads();

    float acc[4][4] = {};
    #pragma unroll
    for (int ks = 0; ks < 4; ++ks) {
        uint32_t ah[4], al[4], bhr[2][4], blr[2][4];
        {
            int koff = ks*16 + (lane >> 4)*8;
            int r = wy*16 + (lane & 15);
            LDSM4(ah, lds_addr(&Qhi[r*LPAD + koff]));
            LDSM4(al, lds_addr(&Qlo[r*LPAD + koff]));
        }
        {
            int nl = (lane & 7) + ((lane >> 4) << 3);
            int kc = ks*16 + ((lane >> 3) & 1)*8;
            #pragma unroll
            for (int p = 0; p < 2; ++p) {
                int nr = wx*32 + p*16 + nl;
                LDSM4(bhr[p], lds_addr(&Khi[nr*LPAD + kc]));
                LDSM4(blr[p], lds_addr(&Klo[nr*LPAD + kc]));
            }
        }
        #pragma unroll
        for (int p = 0; p < 2; ++p) {
            MMA16816(acc[2*p],   ah, bhr[p][0], bhr[p][1]);
            MMA16816(acc[2*p+1], ah, bhr[p][2], bhr[p][3]);
            MMA16816(acc[2*p],   ah, blr[p][0], blr[p][1]);
            MMA16816(acc[2*p+1], ah, blr[p][2], blr[p][3]);
            MMA16816(acc[2*p],   al, bhr[p][0], bhr[p][1]);
            MMA16816(acc[2*p+1], al, bhr[p][2], bhr[p][3]);
        }
    }

    // epilogue: e = exp(x*scale + m*(-1e17)); pack; row sums (no max needed)
    const int lr = lane >> 2, lc = (lane & 3)*2;
    const int r0 = q0 + wy*16 + lr;
    const int r1 = r0 + 8;
    const bool diag = (qb == kb);
    uint32_t* A = attnp + (size_t)bh*S_*S_;
    float s0 = 0.f, s1 = 0.f;

    #pragma unroll
    for (int ni = 0; ni < 4; ++ni) {
        int col = k0 + wx*32 + ni*8 + lc;
        float mk0 = mask[(size_t)b*S_ + col];
        float mk1 = mask[(size_t)b*S_ + col + 1];
        float m00 = fmaxf(mk0, (diag && col   > r0) ? 1.f : 0.f);
        float m01 = fmaxf(mk1, (diag && col+1 > r0) ? 1.f : 0.f);
        float m10 = fmaxf(mk0, (diag && col   > r1) ? 1.f : 0.f);
        float m11 = fmaxf(mk1, (diag && col+1 > r1) ? 1.f : 0.f);
        float e00 = __expf(acc[ni][0]*0.125f + m00*(-1e17f));
        float e01 = __expf(acc[ni][1]*0.125f + m01*(-1e17f));
        float e10 = __expf(acc[ni][2]*0.125f + m10*(-1e17f));
        float e11 = __expf(acc[ni][3]*0.125f + m11*(-1e17f));
        s0 += e00 + e01;
        s1 += e10 + e11;
        *(uint2*)&A[(size_t)r0*S_ + col] = make_uint2(pack_hilo(e00), pack_hilo(e01));
        *(uint2*)&A[(size_t)r1*S_ + col] = make_uint2(pack_hilo(e10), pack_hilo(e11));
    }

    #pragma unroll
    for (int o = 1; o <= 2; o <<= 1) {
        s0 += __shfl_xor_sync(0xffffffffu, s0, o);
        s1 += __shfl_xor_sync(0xffffffffu, s1, o);
    }
    if ((lane & 3) == 0) {
        bsum[wx][wy*16 + lr]     = s0;
        bsum[wx][wy*16 + lr + 8] = s1;
    }
    __syncthreads();
    if (tid < 64)
        g_rsum[((size_t)bh*S_ + q0 + tid)*NQB + kb] = bsum[0][tid] + bsum[1][tid];
}

// ============================================================
// Row sums -> invS (one warp per row)
// ============================================================
__global__ void rowsum_kernel()
{
    const int gw = blockIdx.x*8 + (threadIdx.x >> 5);
    const int lane = threadIdx.x & 31;
    const int row = gw & (S_-1);
    const int n = (row >> 6) + 1;

    float s = (lane < n) ? g_rsum[(size_t)gw*NQB + lane] : 0.f;
    #pragma unroll
    for (int o = 16; o > 0; o >>= 1)
        s += __shfl_xor_sync(0xffffffffu, s, o);
    if (lane == 0)
        g_rowInvS[gw] = 1.0f / s;
}

// ============================================================
// HMMA AV: reads packed e from attn, V^T bf16; 3-pass MMA;
// epilogue scales by invS. grid (NQB, NBH) reversed.
// ============================================================
__global__ void __launch_bounds__(256)
av_hmma(const uint32_t* __restrict__ attnp)
{
    const int bh = blockIdx.y;
    const int qblk = gridDim.x - 1 - blockIdx.x;
    const int q0 = qblk*64;
    const int b = bh >> 4, h = bh & 15;
    const int tid = threadIdx.x;
    const int wid = tid >> 5, lane = tid & 31;
    const int wy = wid & 3, wx = wid >> 2;

    __shared__ __nv_bfloat16 Phi[64*LPAD], Plo[64*LPAD];
    __shared__ __nv_bfloat16 Vhi[64*LPAD], Vlo[64*LPAD];
    __shared__ float sI[64];

    const uint32_t* A = attnp + (size_t)bh*S_*S_;
    const __nv_bfloat16* Vth = g_vthi + (size_t)bh*DEPTH_*S_;
    const __nv_bfloat16* Vtl = g_vtlo + (size_t)bh*DEPTH_*S_;

    if (tid < 64)
        sI[tid] = g_rowInvS[(size_t)bh*S_ + q0 + tid];

    float acc[4][4] = {};

    for (int kb = 0; kb <= qblk; ++kb) {
        const int k0 = kb*64;
        __syncthreads();
        #pragma unroll
        for (int u = 0; u < 2; ++u) {
            int idx = tid + 256*u;
            int r = idx >> 3, c = (idx & 7)*8;
            // packed P: 8 elems = 2 uint4
            const uint4* src = (const uint4*)(A + (size_t)(q0 + r)*S_ + k0 + c);
            uint4 u0 = src[0], u1 = src[1];
            uint4 hi, lo;
            hi.x = __byte_perm(u0.x, u0.y, 0x7632);
            hi.y = __byte_perm(u0.z, u0.w, 0x7632);
            hi.z = __byte_perm(u1.x, u1.y, 0x7632);
            hi.w = __byte_perm(u1.z, u1.w, 0x7632);
            lo.x = __byte_perm(u0.x, u0.y, 0x5410);
            lo.y = __byte_perm(u0.z, u0.w, 0x5410);
            lo.z = __byte_perm(u1.x, u1.y, 0x5410);
            lo.w = __byte_perm(u1.z, u1.w, 0x5410);
            *(uint4*)&Phi[r*LPAD + c] = hi;
            *(uint4*)&Plo[r*LPAD + c] = lo;
            *(uint4*)&Vhi[r*LPAD + c] = *(const uint4*)&Vth[(size_t)r*S_ + k0 + c];
            *(uint4*)&Vlo[r*LPAD + c] = *(const uint4*)&Vtl[(size_t)r*S_ + k0 + c];
        }
        __syncthreads();

        #pragma unroll
        for (int ks = 0; ks < 4; ++ks) {
            uint32_t ah[4], al[4], bhr[2][4], blr[2][4];
            {
                int koff = ks*16 + (lane >> 4)*8;
                int r = wy*16 + (lane & 15);
                LDSM4(ah, lds_addr(&Phi[r*LPAD + koff]));
                LDSM4(al, lds_addr(&Plo[r*LPAD + koff]));
            }
            {
                int nl = (lane & 7) + ((lane >> 4) << 3);
                int kc = ks*16 + ((lane >> 3) & 1)*8;
                #pragma unroll
                for (int p = 0; p < 2; ++p) {
                    int nr = wx*32 + p*16 + nl;
                    LDSM4(bhr[p], lds_addr(&Vhi[nr*LPAD + kc]));
                    LDSM4(blr[p], lds_addr(&Vlo[nr*LPAD + kc]));
                }
            }
            #pragma unroll
            for (int p = 0; p < 2; ++p) {
                MMA16816(acc[2*p],   ah, bhr[p][0], bhr[p][1]);
                MMA16816(acc[2*p+1], ah, bhr[p][2], bhr[p][3]);
                MMA16816(acc[2*p],   ah, blr[p][0], blr[p][1]);
                MMA16816(acc[2*p+1], ah, blr[p][2], blr[p][3]);
                MMA16816(acc[2*p],   al, bhr[p][0], bhr[p][1]);
                MMA16816(acc[2*p+1], al, bhr[p][2], bhr[p][3]);
            }
        }
    }

    // epilogue: scale rows by invS, write g_pre (B,S,D)
    const int lr = lane >> 2, lc = (lane & 3)*2;
    const int rl0 = wy*16 + lr;       // local q row
    const int rl1 = rl0 + 8;
    const float i0 = sI[rl0], i1 = sI[rl1];
    #pragma unroll
    for (int ni = 0; ni < 4; ++ni) {
        int d = wx*32 + ni*8 + lc;
        *(float2*)&g_pre[((size_t)b*S_ + q0 + rl0)*D_ + h*DEPTH_ + d] =
            make_float2(acc[ni][0]*i0, acc[ni][1]*i0);
        *(float2*)&g_pre[((size_t)b*S_ + q0 + rl1)*D_ + h*DEPTH_ + d] =
            make_float2(acc[ni][2]*i1, acc[ni][3]*i1);
    }
}

// ============================================================
// Rescale: unpack e (hi+lo), multiply by invS, write fp32 attn;
// zero upper-triangle blocks. Uniform float4 grid.
// ============================================================
__global__ void __launch_bounds__(256)
rescale_kernel(float* __restrict__ attn)
{
    const size_t idx = (size_t)blockIdx.x*256 + threadIdx.x;   // float4 index
    const int perRow = S_/4;
    const size_t rowg = idx / perRow;
    const int c4 = (int)(idx - rowg*perRow);
    const int qr = (int)(rowg & (S_-1));
    const int kc = c4*4;

    float4* p = (float4*)attn + idx;
    if ((kc >> 6) <= (qr >> 6)) {
        const float I = g_rowInvS[rowg];
        uint4 u = *(const uint4*)p;
        float4 v;
        v.x = (__bfloat162float(__ushort_as_bfloat16((unsigned short)(u.x >> 16)))
             + __bfloat162float(__ushort_as_bfloat16((unsigned short)(u.x & 0xffff)))) * I;
        v.y = (__bfloat162float(__ushort_as_bfloat16((unsigned short)(u.y >> 16)))
             + __bfloat162float(__ushort_as_bfloat16((unsigned short)(u.y & 0xffff)))) * I;
        v.z = (__bfloat162float(__ushort_as_bfloat16((unsigned short)(u.z >> 16)))
             + __bfloat162float(__ushort_as_bfloat16((unsigned short)(u.z & 0xffff)))) * I;
        v.w = (__bfloat162float(__ushort_as_bfloat16((unsigned short)(u.w >> 16)))
             + __bfloat162float(__ushort_as_bfloat16((unsigned short)(u.w & 0xffff)))) * I;
        *p = v;
    } else {
        *p = make_float4(0.f, 0.f, 0.f, 0.f);
    }
}

// ============================================================
extern "C" void kernel_launch(void* const* d_in, const int* in_sizes, int n_in,
                              void* d_out, int out_size)
{
    (void)in_sizes; (void)n_in;
    const float* v    = (const float*)d_in[0];
    const float* k    = (const float*)d_in[1];
    const float* q    = (const float*)d_in[2];
    const float* mask = (const float*)d_in[3];
    const float* Wq   = (const float*)d_in[4];
    const float* bq   = (const float*)d_in[5];
    const float* Wk   = (const float*)d_in[6];
    const float* bk   = (const float*)d_in[7];
    const float* Wv   = (const float*)d_in[8];
    const float* bv   = (const float*)d_in[9];
    const float* Wo   = (const float*)d_in[10];
    const float* bo   = (const float*)d_in[11];

    float* out = (float*)d_out;

    float *qh, *kh, *vh, *pre;
    cudaGetSymbolAddress((void**)&qh, g_qh);
    cudaGetSymbolAddress((void**)&kh, g_kh);
    cudaGetSymbolAddress((void**)&vh, g_vh);
    cudaGetSymbolAddress((void**)&pre, g_pre);
    __nv_bfloat16 *xhi, *xlo, *wthi, *wtlo, *qbhi, *qblo, *kbhi, *kblo;
    cudaGetSymbolAddress((void**)&xhi, g_xhi);
    cudaGetSymbolAddress((void**)&xlo, g_xlo);
    cudaGetSymbolAddress((void**)&wthi, g_wthi);
    cudaGetSymbolAddress((void**)&wtlo, g_wtlo);
    cudaGetSymbolAddress((void**)&qbhi, g_qbhi);
    cudaGetSymbolAddress((void**)&qblo, g_qblo);
    cudaGetSymbolAddress((void**)&kbhi, g_kbhi);
    cudaGetSymbolAddress((void**)&kblo, g_kblo);

    float* attn;
    if ((size_t)out_size >= OUT_ELEMS + ATTN_ELEMS) {
        attn = out + OUT_ELEMS;
    } else {
        cudaGetSymbolAddress((void**)&attn, g_attn_fallback);
    }

    const int n4 = MROWS*KDIM/4;
    dim3 gsplit((n4 + 255)/256);
    dim3 gwt(32, 32), twt(32, 8);
    dim3 ggemm(KDIM/128, MROWS/128);

    // projections
    split_kernel<<<gsplit, 256>>>((const float4*)q, (uint2*)xhi, (uint2*)xlo, n4);
    wsplit_kernel<<<gwt, twt>>>(Wq, wthi, wtlo);
    gemm_hmma<<<ggemm, 256>>>(xhi, xlo, wthi, wtlo, bq, qh, 1);
    split_kernel<<<gsplit, 256>>>((const float4*)k, (uint2*)xhi, (uint2*)xlo, n4);
    wsplit_kernel<<<gwt, twt>>>(Wk, wthi, wtlo);
    gemm_hmma<<<ggemm, 256>>>(xhi, xlo, wthi, wtlo, bk, kh, 1);
    split_kernel<<<gsplit, 256>>>((const float4*)v, (uint2*)xhi, (uint2*)xlo, n4);
    wsplit_kernel<<<gwt, twt>>>(Wv, wthi, wtlo);
    gemm_hmma<<<ggemm, 256>>>(xhi, xlo, wthi, wtlo, bv, vh, 1);

    // bf16 prep for attention
    const int nqk4 = NBH*S_*DEPTH_/4;
    dim3 gq((nqk4 + 255)/256);
    split_kernel<<<gq, 256>>>((const float4*)qh, (uint2*)qbhi, (uint2*)qblo, nqk4);
    split_kernel<<<gq, 256>>>((const float4*)kh, (uint2*)kbhi, (uint2*)kblo, nqk4);
    dim3 gvt(S_/32, DEPTH_/32, NBH);
    vtsplit_kernel<<<gvt, twt>>>();

    // attention
    dim3 glog(NTRI, NBH);
    logits_hmma<<<glog, 256>>>(mask, (uint32_t*)attn);
    rowsum_kernel<<<NBH*S_/8, 256>>>();
    dim3 gav(NQB, NBH);
    av_hmma<<<gav, 256>>>((const uint32_t*)attn);
    rescale_kernel<<<(int)(ATTN_ELEMS/4/256), 256>>>(attn);

    // output projection
    split_kernel<<<gsplit, 256>>>((const float4*)pre, (uint2*)xhi, (uint2*)xlo, n4);
    wsplit_kernel<<<gwt, twt>>>(Wo, wthi, wtlo);
    gemm_hmma<<<ggemm, 256>>>(xhi, xlo, wthi, wtlo, bo, out, 0);
}

// round 9
// speedup vs baseline: 2.0057x; 1.0526x over previous
#include <cuda_runtime.h>
#include <cuda_bf16.h>
#include <math.h>
#include <stdint.h>

#define B_  2
#define S_  2048
#define D_  1024
#define H_  16
#define DEPTH_ 64
#define MROWS (B_*S_)          // 4096
#define KDIM 1024
#define NBH (B_*H_)            // 32
#define NQB (S_/64)            // 32
#define NTRI (NQB*(NQB+1)/2)   // 528
#define OUT_ELEMS  ((size_t)B_*S_*D_)
#define ATTN_ELEMS ((size_t)B_*H_*S_*S_)

// ---- static device scratch ----
__device__ float g_vh[B_*H_*S_*DEPTH_];
__device__ float g_attn_fallback[1];
__device__ __align__(256) __nv_bfloat16 g_xhi[MROWS*KDIM];
__device__ __align__(256) __nv_bfloat16 g_xlo[MROWS*KDIM];
__device__ __align__(256) __nv_bfloat16 g_wthi[KDIM*KDIM];
__device__ __align__(256) __nv_bfloat16 g_wtlo[KDIM*KDIM];
__device__ __align__(256) __nv_bfloat16 g_qbhi[NBH*S_*DEPTH_];
__device__ __align__(256) __nv_bfloat16 g_qblo[NBH*S_*DEPTH_];
__device__ __align__(256) __nv_bfloat16 g_kbhi[NBH*S_*DEPTH_];
__device__ __align__(256) __nv_bfloat16 g_kblo[NBH*S_*DEPTH_];
__device__ __align__(256) __nv_bfloat16 g_vthi[NBH*DEPTH_*S_];
__device__ __align__(256) __nv_bfloat16 g_vtlo[NBH*DEPTH_*S_];
__device__ float g_rsum[NBH*S_*NQB];
__device__ float g_rowInvS[NBH*S_];

// ============================================================
// helpers
// ============================================================
__device__ __forceinline__ uint32_t lds_addr(const void* p) {
    return (uint32_t)__cvta_generic_to_shared(p);
}

#define LDSM4(r, addr) \
    asm volatile("ldmatrix.sync.aligned.m8n8.x4.shared.b16 {%0,%1,%2,%3}, [%4];" \
        : "=r"((r)[0]), "=r"((r)[1]), "=r"((r)[2]), "=r"((r)[3]) : "r"(addr))

#define MMA16816(c, a, b0, b1) \
    asm volatile("mma.sync.aligned.m16n8k16.row.col.f32.bf16.bf16.f32 " \
        "{%0,%1,%2,%3}, {%4,%5,%6,%7}, {%8,%9}, {%0,%1,%2,%3};" \
        : "+f"((c)[0]), "+f"((c)[1]), "+f"((c)[2]), "+f"((c)[3]) \
        : "r"((a)[0]), "r"((a)[1]), "r"((a)[2]), "r"((a)[3]), "r"(b0), "r"(b1))

#define CP16(sdst, gsrc) \
    asm volatile("cp.async.cg.shared.global [%0], [%1], 16;" :: "r"(sdst), "l"(gsrc))
#define CP_COMMIT() asm volatile("cp.async.commit_group;")

__device__ __forceinline__ uint32_t pack_hilo(float e) {
    __nv_bfloat16 h = __float2bfloat16(e);
    __nv_bfloat16 l = __float2bfloat16(e - __bfloat162float(h));
    return ((uint32_t)__bfloat16_as_ushort(h) << 16) | (uint32_t)__bfloat16_as_ushort(l);
}
__device__ __forceinline__ __nv_bfloat162 split2(float a, float b, __nv_bfloat162* lo2) {
    __nv_bfloat16 ha = __float2bfloat16(a), hb = __float2bfloat16(b);
    __nv_bfloat16 la = __float2bfloat16(a - __bfloat162float(ha));
    __nv_bfloat16 lb = __float2bfloat16(b - __bfloat162float(hb));
    *lo2 = __nv_bfloat162(la, lb);
    return __nv_bfloat162(ha, hb);
}

// ============================================================
// Split fp32 -> bf16 hi/lo (inputs q,k,v)
// ============================================================
__global__ void split_kernel(const float4* __restrict__ x,
                             uint2* __restrict__ hi, uint2* __restrict__ lo, int n4)
{
    int i = blockIdx.x*256 + threadIdx.x;
    if (i >= n4) return;
    float4 v = x[i];
    __nv_bfloat16 h0 = __float2bfloat16(v.x), h1 = __float2bfloat16(v.y);
    __nv_bfloat16 h2 = __float2bfloat16(v.z), h3 = __float2bfloat16(v.w);
    __nv_bfloat16 l0 = __float2bfloat16(v.x - __bfloat162float(h0));
    __nv_bfloat16 l1 = __float2bfloat16(v.y - __bfloat162float(h1));
    __nv_bfloat16 l2 = __float2bfloat16(v.z - __bfloat162float(h2));
    __nv_bfloat16 l3 = __float2bfloat16(v.w - __bfloat162float(h3));
    union { __nv_bfloat16 h[4]; uint2 u; } ph, pl;
    ph.h[0]=h0; ph.h[1]=h1; ph.h[2]=h2; ph.h[3]=h3;
    pl.h[0]=l0; pl.h[1]=l1; pl.h[2]=l2; pl.h[3]=l3;
    hi[i] = ph.u;
    lo[i] = pl.u;
}

// ============================================================
// W [k][n] fp32 -> W^T hi/lo bf16 [n][k]
// ============================================================
__global__ void wsplit_kernel(const float* __restrict__ W,
                              __nv_bfloat16* __restrict__ thi,
                              __nv_bfloat16* __restrict__ tlo)
{
    __shared__ float ts[32][33];
    const int k0 = blockIdx.x*32, n0 = blockIdx.y*32;
    const int tx = threadIdx.x, ty = threadIdx.y;
    #pragma unroll
    for (int u = 0; u < 4; ++u)
        ts[ty + 8*u][tx] = W[(size_t)(k0 + ty + 8*u)*KDIM + n0 + tx];
    __syncthreads();
    #pragma unroll
    for (int u = 0; u < 4; ++u) {
        float v = ts[tx][ty + 8*u];
        __nv_bfloat16 h = __float2bfloat16(v);
        __nv_bfloat16 l = __float2bfloat16(v - __bfloat162float(h));
        size_t idx = (size_t)(n0 + ty + 8*u)*KDIM + k0 + tx;
        thi[idx] = h;
        tlo[idx] = l;
    }
}

// ============================================================
// V [bh][s][d] -> V^T hi/lo bf16 [bh][d][s]
// ============================================================
__global__ void vtsplit_kernel()
{
    __shared__ float ts[32][33];
    const int s0 = blockIdx.x*32, d0 = blockIdx.y*32;
    const int bh = blockIdx.z;
    const int tx = threadIdx.x, ty = threadIdx.y;
    const float* V = g_vh + (size_t)bh*S_*DEPTH_;
    #pragma unroll
    for (int u = 0; u < 4; ++u)
        ts[ty + 8*u][tx] = V[(size_t)(s0 + ty + 8*u)*DEPTH_ + d0 + tx];
    __syncthreads();
    #pragma unroll
    for (int u = 0; u < 4; ++u) {
        float v = ts[tx][ty + 8*u];
        __nv_bfloat16 h = __float2bfloat16(v);
        __nv_bfloat16 l = __float2bfloat16(v - __bfloat162float(h));
        size_t idx = ((size_t)bh*DEPTH_ + d0 + ty + 8*u)*S_ + s0 + tx;
        g_vthi[idx] = h;
        g_vtlo[idx] = l;
    }
}

// ============================================================
// Pipelined HMMA split-bf16 GEMM (cp.async 2-stage, dyn smem 80KB)
// smem layout (elements): Ahi[2*TSZ] | Alo[2*TSZ] | Bhi[2*TSZ] | Blo[2*TSZ]
// byte offsets from Ahi region: Alo +4*TSZ, Bhi +8*TSZ, Blo +12*TSZ
// out_mode: 0 = flat fp32, 1 = headed fp32, 2 = headed bf16 hi/lo
// ============================================================
#define PADE 40
#define TSZ  (128*PADE)   // elems per tile buffer (5120)

__global__ void __launch_bounds__(256)
gemm_hmma(const __nv_bfloat16* __restrict__ Ahi,
          const __nv_bfloat16* __restrict__ Alo,
          const __nv_bfloat16* __restrict__ Bhi,
          const __nv_bfloat16* __restrict__ Blo,
          const float* __restrict__ bias,
          float* __restrict__ out,
          __nv_bfloat16* __restrict__ ohi,
          __nv_bfloat16* __restrict__ olo,
          int out_mode)
{
    extern __shared__ __nv_bfloat16 sm[];
    __nv_bfloat16* sAh = sm;
    __nv_bfloat16* sAl = sm + 2*TSZ;
    __nv_bfloat16* sBh = sm + 4*TSZ;
    __nv_bfloat16* sBl = sm + 6*TSZ;

    const int tid = threadIdx.x;
    const int wid = tid >> 5, lane = tid & 31;
    const int wy = wid & 3;
    const int wx = wid >> 2;
    const int m0 = blockIdx.y * 128;
    const int n0 = blockIdx.x * 128;

    const int lr_ = tid >> 2;            // 0..63 row base
    const int lcb = (tid & 3) * 8;       // k elem offset

    float acc[2][8][4];
    #pragma unroll
    for (int mi = 0; mi < 2; ++mi)
        #pragma unroll
        for (int ni = 0; ni < 8; ++ni)
            #pragma unroll
            for (int c = 0; c < 4; ++c) acc[mi][ni][c] = 0.f;

    const int nkt = KDIM/32;

    // byte distances between regions (2*TSZ elements * 2 bytes)
    const uint32_t REG = 4*TSZ;   // bytes

    auto load_tile = [&](int kt, int st) {
        #pragma unroll
        for (int u = 0; u < 2; ++u) {
            int r = lr_ + 64*u;
            size_t ga = (size_t)(m0 + r)*KDIM + kt*32 + lcb;
            size_t gb = (size_t)(n0 + r)*KDIM + kt*32 + lcb;
            uint32_t so = lds_addr(&sAh[(size_t)st*TSZ + r*PADE + lcb]);
            CP16(so,         &Ahi[ga]);
            CP16(so + REG,   &Alo[ga]);
            CP16(so + 2*REG, &Bhi[gb]);
            CP16(so + 3*REG, &Blo[gb]);
        }
        CP_COMMIT();
    };

    load_tile(0, 0);

    for (int kt = 0; kt < nkt; ++kt) {
        const int st = kt & 1;
        if (kt + 1 < nkt) {
            load_tile(kt + 1, (kt + 1) & 1);
            asm volatile("cp.async.wait_group 1;");
        } else {
            asm volatile("cp.async.wait_group 0;");
        }
        __syncthreads();

        const __nv_bfloat16* Ah_ = sAh + st*TSZ;
        const __nv_bfloat16* Al_ = sAl + st*TSZ;
        const __nv_bfloat16* Bh_ = sBh + st*TSZ;
        const __nv_bfloat16* Bl_ = sBl + st*TSZ;

        #pragma unroll
        for (int ks = 0; ks < 2; ++ks) {
            uint32_t ahi[2][4], alo[2][4], bhi[4][4], blo[4][4];
            {
                int koff = ks*16 + (lane >> 4)*8;
                int r = wy*32 + (lane & 15);
                LDSM4(ahi[0], lds_addr(&Ah_[r*PADE + koff]));
                LDSM4(ahi[1], lds_addr(&Ah_[(r+16)*PADE + koff]));
                LDSM4(alo[0], lds_addr(&Al_[r*PADE + koff]));
                LDSM4(alo[1], lds_addr(&Al_[(r+16)*PADE + koff]));
            }
            {
                int nl = (lane & 7) + ((lane >> 4) << 3);
                int kc = ks*16 + ((lane >> 3) & 1)*8;
                #pragma unroll
                for (int p = 0; p < 4; ++p) {
                    int nr = wx*64 + p*16 + nl;
                    LDSM4(bhi[p], lds_addr(&Bh_[nr*PADE + kc]));
                    LDSM4(blo[p], lds_addr(&Bl_[nr*PADE + kc]));
                }
            }
            #pragma unroll
            for (int mi = 0; mi < 2; ++mi) {
                #pragma unroll
                for (int p = 0; p < 4; ++p) {
                    MMA16816(acc[mi][2*p],   ahi[mi], bhi[p][0], bhi[p][1]);
                    MMA16816(acc[mi][2*p+1], ahi[mi], bhi[p][2], bhi[p][3]);
                    MMA16816(acc[mi][2*p],   ahi[mi], blo[p][0], blo[p][1]);
                    MMA16816(acc[mi][2*p+1], ahi[mi], blo[p][2], blo[p][3]);
                    MMA16816(acc[mi][2*p],   alo[mi], bhi[p][0], bhi[p][1]);
                    MMA16816(acc[mi][2*p+1], alo[mi], bhi[p][2], bhi[p][3]);
                }
            }
        }
        __syncthreads();
    }

    const int lr = lane >> 2, lc = (lane & 3)*2;
    #pragma unroll
    for (int mi = 0; mi < 2; ++mi) {
        #pragma unroll
        for (int ni = 0; ni < 8; ++ni) {
            int col = n0 + wx*64 + ni*8 + lc;
            float b0 = bias[col], b1 = bias[col+1];
            #pragma unroll
            for (int half = 0; half < 2; ++half) {
                int row = m0 + wy*32 + mi*16 + lr + half*8;
                float v0 = acc[mi][ni][half*2]   + b0;
                float v1 = acc[mi][ni][half*2+1] + b1;
                if (out_mode == 0) {
                    *(float2*)&out[(size_t)row*D_ + col] = make_float2(v0, v1);
                } else {
                    int b = row >> 11, s = row & 2047;
                    int h = col >> 6, d = col & 63;
                    size_t idx = (((size_t)(b*H_ + h))*S_ + s)*DEPTH_ + d;
                    if (out_mode == 1) {
                        out[idx]     = v0;
                        out[idx + 1] = v1;
                    } else {
                        __nv_bfloat162 lo2;
                        __nv_bfloat162 hi2 = split2(v0, v1, &lo2);
                        *(__nv_bfloat162*)&ohi[idx] = hi2;
                        *(__nv_bfloat162*)&olo[idx] = lo2;
                    }
                }
            }
        }
    }
}

// ============================================================
// HMMA logits (R7, measured good)
// ============================================================
#define LPAD 72

__global__ void __launch_bounds__(256)
logits_hmma(const float* __restrict__ mask, uint32_t* __restrict__ attnp)
{
    const int bh = blockIdx.y;
    const int b  = bh >> 4;
    int t = blockIdx.x;
    int qb = (int)((sqrtf(8.f*t + 1.f) - 1.f) * 0.5f);
    while ((qb+1)*(qb+2)/2 <= t) ++qb;
    while (qb*(qb+1)/2 > t) --qb;
    const int kb = t - qb*(qb+1)/2;
    const int q0 = qb*64, k0 = kb*64;

    const int tid = threadIdx.x;
    const int wid = tid >> 5, lane = tid & 31;
    const int wy = wid & 3, wx = wid >> 2;

    __shared__ __nv_bfloat16 Qhi[64*LPAD], Qlo[64*LPAD];
    __shared__ __nv_bfloat16 Khi[64*LPAD], Klo[64*LPAD];
    __shared__ float bsum[2][64];

    const __nv_bfloat16* Qh = g_qbhi + ((size_t)bh*S_ + q0)*DEPTH_;
    const __nv_bfloat16* Ql = g_qblo + ((size_t)bh*S_ + q0)*DEPTH_;
    const __nv_bfloat16* Kh = g_kbhi + ((size_t)bh*S_ + k0)*DEPTH_;
    const __nv_bfloat16* Kl = g_kblo + ((size_t)bh*S_ + k0)*DEPTH_;

    #pragma unroll
    for (int u = 0; u < 2; ++u) {
        int idx = tid + 256*u;
        int r = idx >> 3, c = (idx & 7)*8;
        *(uint4*)&Qhi[r*LPAD + c] = *(const uint4*)&Qh[r*DEPTH_ + c];
        *(uint4*)&Qlo[r*LPAD + c] = *(const uint4*)&Ql[r*DEPTH_ + c];
        *(uint4*)&Khi[r*LPAD + c] = *(const uint4*)&Kh[r*DEPTH_ + c];
        *(uint4*)&Klo[r*LPAD + c] = *(const uint4*)&Kl[r*DEPTH_ + c];
    }
    __syncthreads();

    float acc[4][4] = {};
    #pragma unroll
    for (int ks = 0; ks < 4; ++ks) {
        uint32_t ah[4], al[4], bhr[2][4], blr[2][4];
        {
            int koff = ks*16 + (lane >> 4)*8;
            int r = wy*16 + (lane & 15);
            LDSM4(ah, lds_addr(&Qhi[r*LPAD + koff]));
            LDSM4(al, lds_addr(&Qlo[r*LPAD + koff]));
        }
        {
            int nl = (lane & 7) + ((lane >> 4) << 3);
            int kc = ks*16 + ((lane >> 3) & 1)*8;
            #pragma unroll
            for (int p = 0; p < 2; ++p) {
                int nr = wx*32 + p*16 + nl;
                LDSM4(bhr[p], lds_addr(&Khi[nr*LPAD + kc]));
                LDSM4(blr[p], lds_addr(&Klo[nr*LPAD + kc]));
            }
        }
        #pragma unroll
        for (int p = 0; p < 2; ++p) {
            MMA16816(acc[2*p],   ah, bhr[p][0], bhr[p][1]);
            MMA16816(acc[2*p+1], ah, bhr[p][2], bhr[p][3]);
            MMA16816(acc[2*p],   ah, blr[p][0], blr[p][1]);
            MMA16816(acc[2*p+1], ah, blr[p][2], blr[p][3]);
            MMA16816(acc[2*p],   al, bhr[p][0], bhr[p][1]);
            MMA16816(acc[2*p+1], al, bhr[p][2], bhr[p][3]);
        }
    }

    const int lr = lane >> 2, lc = (lane & 3)*2;
    const int r0 = q0 + wy*16 + lr;
    const int r1 = r0 + 8;
    const bool diag = (qb == kb);
    uint32_t* A = attnp + (size_t)bh*S_*S_;
    float s0 = 0.f, s1 = 0.f;

    #pragma unroll
    for (int ni = 0; ni < 4; ++ni) {
        int col = k0 + wx*32 + ni*8 + lc;
        float mk0 = mask[(size_t)b*S_ + col];
        float mk1 = mask[(size_t)b*S_ + col + 1];
        float m00 = fmaxf(mk0, (diag && col   > r0) ? 1.f : 0.f);
        float m01 = fmaxf(mk1, (diag && col+1 > r0) ? 1.f : 0.f);
        float m10 = fmaxf(mk0, (diag && col   > r1) ? 1.f : 0.f);
        float m11 = fmaxf(mk1, (diag && col+1 > r1) ? 1.f : 0.f);
        float e00 = __expf(acc[ni][0]*0.125f + m00*(-1e17f));
        float e01 = __expf(acc[ni][1]*0.125f + m01*(-1e17f));
        float e10 = __expf(acc[ni][2]*0.125f + m10*(-1e17f));
        float e11 = __expf(acc[ni][3]*0.125f + m11*(-1e17f));
        s0 += e00 + e01;
        s1 += e10 + e11;
        *(uint2*)&A[(size_t)r0*S_ + col] = make_uint2(pack_hilo(e00), pack_hilo(e01));
        *(uint2*)&A[(size_t)r1*S_ + col] = make_uint2(pack_hilo(e10), pack_hilo(e11));
    }

    #pragma unroll
    for (int o = 1; o <= 2; o <<= 1) {
        s0 += __shfl_xor_sync(0xffffffffu, s0, o);
        s1 += __shfl_xor_sync(0xffffffffu, s1, o);
    }
    if ((lane & 3) == 0) {
        bsum[wx][wy*16 + lr]     = s0;
        bsum[wx][wy*16 + lr + 8] = s1;
    }
    __syncthreads();
    if (tid < 64)
        g_rsum[((size_t)bh*S_ + q0 + tid)*NQB + kb] = bsum[0][tid] + bsum[1][tid];
}

// ============================================================
// Row sums -> invS
// ============================================================
__global__ void rowsum_kernel()
{
    const int gw = blockIdx.x*8 + (threadIdx.x >> 5);
    const int lane = threadIdx.x & 31;
    const int row = gw & (S_-1);
    const int n = (row >> 6) + 1;

    float s = (lane < n) ? g_rsum[(size_t)gw*NQB + lane] : 0.f;
    #pragma unroll
    for (int o = 16; o > 0; o >>= 1)
        s += __shfl_xor_sync(0xffffffffu, s, o);
    if (lane == 0)
        g_rowInvS[gw] = 1.0f / s;
}

// ============================================================
// HMMA AV: epilogue writes bf16 hi/lo directly into xhi/xlo.
// ============================================================
__global__ void __launch_bounds__(256)
av_hmma(const uint32_t* __restrict__ attnp)
{
    const int bh = blockIdx.y;
    const int qblk = gridDim.x - 1 - blockIdx.x;
    const int q0 = qblk*64;
    const int b = bh >> 4, h = bh & 15;
    const int tid = threadIdx.x;
    const int wid = tid >> 5, lane = tid & 31;
    const int wy = wid & 3, wx = wid >> 2;

    __shared__ __nv_bfloat16 Phi[64*LPAD], Plo[64*LPAD];
    __shared__ __nv_bfloat16 Vhi[64*LPAD], Vlo[64*LPAD];
    __shared__ float sI[64];

    const uint32_t* A = attnp + (size_t)bh*S_*S_;
    const __nv_bfloat16* Vth = g_vthi + (size_t)bh*DEPTH_*S_;
    const __nv_bfloat16* Vtl = g_vtlo + (size_t)bh*DEPTH_*S_;

    if (tid < 64)
        sI[tid] = g_rowInvS[(size_t)bh*S_ + q0 + tid];

    float acc[4][4] = {};

    for (int kb = 0; kb <= qblk; ++kb) {
        const int k0 = kb*64;
        __syncthreads();
        #pragma unroll
        for (int u = 0; u < 2; ++u) {
            int idx = tid + 256*u;
            int r = idx >> 3, c = (idx & 7)*8;
            const uint4* src = (const uint4*)(A + (size_t)(q0 + r)*S_ + k0 + c);
            uint4 u0 = src[0], u1 = src[1];
            uint4 hi, lo;
            hi.x = __byte_perm(u0.x, u0.y, 0x7632);
            hi.y = __byte_perm(u0.z, u0.w, 0x7632);
            hi.z = __byte_perm(u1.x, u1.y, 0x7632);
            hi.w = __byte_perm(u1.z, u1.w, 0x7632);
            lo.x = __byte_perm(u0.x, u0.y, 0x5410);
            lo.y = __byte_perm(u0.z, u0.w, 0x5410);
            lo.z = __byte_perm(u1.x, u1.y, 0x5410);
            lo.w = __byte_perm(u1.z, u1.w, 0x5410);
            *(uint4*)&Phi[r*LPAD + c] = hi;
            *(uint4*)&Plo[r*LPAD + c] = lo;
            *(uint4*)&Vhi[r*LPAD + c] = *(const uint4*)&Vth[(size_t)r*S_ + k0 + c];
            *(uint4*)&Vlo[r*LPAD + c] = *(const uint4*)&Vtl[(size_t)r*S_ + k0 + c];
        }
        __syncthreads();

        #pragma unroll
        for (int ks = 0; ks < 4; ++ks) {
            uint32_t ah[4], al[4], bhr[2][4], blr[2][4];
            {
                int koff = ks*16 + (lane >> 4)*8;
                int r = wy*16 + (lane & 15);
                LDSM4(ah, lds_addr(&Phi[r*LPAD + koff]));
                LDSM4(al, lds_addr(&Plo[r*LPAD + koff]));
            }
            {
                int nl = (lane & 7) + ((lane >> 4) << 3);
                int kc = ks*16 + ((lane >> 3) & 1)*8;
                #pragma unroll
                for (int p = 0; p < 2; ++p) {
                    int nr = wx*32 + p*16 + nl;
                    LDSM4(bhr[p], lds_addr(&Vhi[nr*LPAD + kc]));
                    LDSM4(blr[p], lds_addr(&Vlo[nr*LPAD + kc]));
                }
            }
            #pragma unroll
            for (int p = 0; p < 2; ++p) {
                MMA16816(acc[2*p],   ah, bhr[p][0], bhr[p][1]);
                MMA16816(acc[2*p+1], ah, bhr[p][2], bhr[p][3]);
                MMA16816(acc[2*p],   ah, blr[p][0], blr[p][1]);
                MMA16816(acc[2*p+1], ah, blr[p][2], blr[p][3]);
                MMA16816(acc[2*p],   al, bhr[p][0], bhr[p][1]);
                MMA16816(acc[2*p+1], al, bhr[p][2], bhr[p][3]);
            }
        }
    }

    const int lr = lane >> 2, lc = (lane & 3)*2;
    const int rl0 = wy*16 + lr;
    const int rl1 = rl0 + 8;
    const float i0 = sI[rl0], i1 = sI[rl1];
    #pragma unroll
    for (int ni = 0; ni < 4; ++ni) {
        int d = wx*32 + ni*8 + lc;
        size_t idx0 = (size_t)(b*S_ + q0 + rl0)*D_ + h*DEPTH_ + d;
        size_t idx1 = (size_t)(b*S_ + q0 + rl1)*D_ + h*DEPTH_ + d;
        __nv_bfloat162 lo2;
        __nv_bfloat162 hi2 = split2(acc[ni][0]*i0, acc[ni][1]*i0, &lo2);
        *(__nv_bfloat162*)&g_xhi[idx0] = hi2;
        *(__nv_bfloat162*)&g_xlo[idx0] = lo2;
        hi2 = split2(acc[ni][2]*i1, acc[ni][3]*i1, &lo2);
        *(__nv_bfloat162*)&g_xhi[idx1] = hi2;
        *(__nv_bfloat162*)&g_xlo[idx1] = lo2;
    }
}

// ============================================================
// Rescale attn in place; zero upper blocks.
// ============================================================
__global__ void __launch_bounds__(256)
rescale_kernel(float* __restrict__ attn)
{
    const size_t idx = (size_t)blockIdx.x*256 + threadIdx.x;
    const int perRow = S_/4;
    const size_t rowg = idx / perRow;
    const int c4 = (int)(idx - rowg*perRow);
    const int qr = (int)(rowg & (S_-1));
    const int kc = c4*4;

    float4* p = (float4*)attn + idx;
    if ((kc >> 6) <= (qr >> 6)) {
        const float I = g_rowInvS[rowg];
        uint4 u = *(const uint4*)p;
        float4 v;
        v.x = (__bfloat162float(__ushort_as_bfloat16((unsigned short)(u.x >> 16)))
             + __bfloat162float(__ushort_as_bfloat16((unsigned short)(u.x & 0xffff)))) * I;
        v.y = (__bfloat162float(__ushort_as_bfloat16((unsigned short)(u.y >> 16)))
             + __bfloat162float(__ushort_as_bfloat16((unsigned short)(u.y & 0xffff)))) * I;
        v.z = (__bfloat162float(__ushort_as_bfloat16((unsigned short)(u.z >> 16)))
             + __bfloat162float(__ushort_as_bfloat16((unsigned short)(u.z & 0xffff)))) * I;
        v.w = (__bfloat162float(__ushort_as_bfloat16((unsigned short)(u.w >> 16)))
             + __bfloat162float(__ushort_as_bfloat16((unsigned short)(u.w & 0xffff)))) * I;
        *p = v;
    } else {
        *p = make_float4(0.f, 0.f, 0.f, 0.f);
    }
}

// ============================================================
extern "C" void kernel_launch(void* const* d_in, const int* in_sizes, int n_in,
                              void* d_out, int out_size)
{
    (void)in_sizes; (void)n_in;
    const float* v    = (const float*)d_in[0];
    const float* k    = (const float*)d_in[1];
    const float* q    = (const float*)d_in[2];
    const float* mask = (const float*)d_in[3];
    const float* Wq   = (const float*)d_in[4];
    const float* bq   = (const float*)d_in[5];
    const float* Wk   = (const float*)d_in[6];
    const float* bk   = (const float*)d_in[7];
    const float* Wv   = (const float*)d_in[8];
    const float* bv   = (const float*)d_in[9];
    const float* Wo   = (const float*)d_in[10];
    const float* bo   = (const float*)d_in[11];

    float* out = (float*)d_out;

    float *vh;
    cudaGetSymbolAddress((void**)&vh, g_vh);
    __nv_bfloat16 *xhi, *xlo, *wthi, *wtlo, *qbhi, *qblo, *kbhi, *kblo;
    cudaGetSymbolAddress((void**)&xhi, g_xhi);
    cudaGetSymbolAddress((void**)&xlo, g_xlo);
    cudaGetSymbolAddress((void**)&wthi, g_wthi);
    cudaGetSymbolAddress((void**)&wtlo, g_wtlo);
    cudaGetSymbolAddress((void**)&qbhi, g_qbhi);
    cudaGetSymbolAddress((void**)&qblo, g_qblo);
    cudaGetSymbolAddress((void**)&kbhi, g_kbhi);
    cudaGetSymbolAddress((void**)&kblo, g_kblo);

    float* attn;
    if ((size_t)out_size >= OUT_ELEMS + ATTN_ELEMS) {
        attn = out + OUT_ELEMS;
    } else {
        cudaGetSymbolAddress((void**)&attn, g_attn_fallback);
    }

    const int GEMM_SMEM = 8*TSZ*2;   // 81920 bytes
    cudaFuncSetAttribute(gemm_hmma,
                         cudaFuncAttributeMaxDynamicSharedMemorySize, GEMM_SMEM);

    const int n4 = MROWS*KDIM/4;
    dim3 gsplit((n4 + 255)/256);
    dim3 gwt(32, 32), twt(32, 8);
    dim3 ggemm(KDIM/128, MROWS/128);

    // Q projection -> bf16 hi/lo headed (fused split)
    split_kernel<<<gsplit, 256>>>((const float4*)q, (uint2*)xhi, (uint2*)xlo, n4);
    wsplit_kernel<<<gwt, twt>>>(Wq, wthi, wtlo);
    gemm_hmma<<<ggemm, 256, GEMM_SMEM>>>(xhi, xlo, wthi, wtlo, bq, nullptr, qbhi, qblo, 2);
    // K projection -> bf16 hi/lo headed
    split_kernel<<<gsplit, 256>>>((const float4*)k, (uint2*)xhi, (uint2*)xlo, n4);
    wsplit_kernel<<<gwt, twt>>>(Wk, wthi, wtlo);
    gemm_hmma<<<ggemm, 256, GEMM_SMEM>>>(xhi, xlo, wthi, wtlo, bk, nullptr, kbhi, kblo, 2);
    // V projection -> fp32 headed (for transpose)
    split_kernel<<<gsplit, 256>>>((const float4*)v, (uint2*)xhi, (uint2*)xlo, n4);
    wsplit_kernel<<<gwt, twt>>>(Wv, wthi, wtlo);
    gemm_hmma<<<ggemm, 256, GEMM_SMEM>>>(xhi, xlo, wthi, wtlo, bv, vh, nullptr, nullptr, 1);
    dim3 gvt(S_/32, DEPTH_/32, NBH);
    vtsplit_kernel<<<gvt, twt>>>();

    // attention
    dim3 glog(NTRI, NBH);
    logits_hmma<<<glog, 256>>>(mask, (uint32_t*)attn);
    rowsum_kernel<<<NBH*S_/8, 256>>>();
    dim3 gav(NQB, NBH);
    av_hmma<<<gav, 256>>>((const uint32_t*)attn);   // writes xhi/xlo
    rescale_kernel<<<(int)(ATTN_ELEMS/4/256), 256>>>(attn);

    // output projection (consumes xhi/xlo from av_hmma)
    wsplit_kernel<<<gwt, twt>>>(Wo, wthi, wtlo);
    gemm_hmma<<<ggemm, 256, GEMM_SMEM>>>(xhi, xlo, wthi, wtlo, bo, out, nullptr, nullptr, 0);
}